// round 1
// baseline (speedup 1.0000x reference)
#include <cuda_runtime.h>
#include <math_constants.h>

// Problem constants
#define B_SZ 2
#define S_SZ 2048
#define D_SZ 1024
#define H_SZ 16
#define HD_SZ 64
#define BH_SZ (B_SZ * H_SZ)       // 32
#define TOK_SZ (B_SZ * S_SZ)      // 4096

// Scratch (device globals: allocation-free rule)
__device__ float g_Q[BH_SZ * S_SZ * HD_SZ];  // [b,h,s,d] 16MB
__device__ float g_K[BH_SZ * S_SZ * HD_SZ];
__device__ float g_V[BH_SZ * S_SZ * HD_SZ];
__device__ float g_M[BH_SZ * S_SZ];          // per-row running max
__device__ float g_L[BH_SZ * S_SZ];          // per-row sum of exp
__device__ float g_w[BH_SZ * S_SZ];          // per-key mean prob weight

// ---------------------------------------------------------------------------
// Projection GEMM: out[b,h,s,d] = (X @ W + bias)  with head-split layout.
// 64x64 tile, K-chunk 64, 256 threads, 4x4 per-thread microtile.
// ---------------------------------------------------------------------------
__global__ __launch_bounds__(256) void proj_kernel(const float* __restrict__ X,
                                                   const float* __restrict__ W,
                                                   const float* __restrict__ bias,
                                                   int sel) {
    __shared__ float Xs[64][65];
    __shared__ float Ws[64][65];
    float* outp = (sel == 0) ? g_Q : (sel == 1) ? g_K : g_V;

    const int tid = threadIdx.x;
    const int tx = tid & 15, ty = tid >> 4;
    const int m0 = blockIdx.y * 64;
    const int n0 = blockIdx.x * 64;

    float acc[4][4] = {};

    for (int k0 = 0; k0 < D_SZ; k0 += 64) {
        __syncthreads();
        #pragma unroll
        for (int i = tid; i < 1024; i += 256) {
            int r = i >> 4, c = (i & 15) << 2;
            float4 v = *(const float4*)(X + (size_t)(m0 + r) * D_SZ + k0 + c);
            Xs[r][c] = v.x; Xs[r][c + 1] = v.y; Xs[r][c + 2] = v.z; Xs[r][c + 3] = v.w;
            float4 u = *(const float4*)(W + (size_t)(k0 + r) * D_SZ + n0 + c);
            Ws[r][c] = u.x; Ws[r][c + 1] = u.y; Ws[r][c + 2] = u.z; Ws[r][c + 3] = u.w;
        }
        __syncthreads();
        #pragma unroll 8
        for (int k = 0; k < 64; ++k) {
            float a[4], b[4];
            #pragma unroll
            for (int i = 0; i < 4; ++i) a[i] = Xs[ty * 4 + i][k];
            #pragma unroll
            for (int j = 0; j < 4; ++j) b[j] = Ws[k][tx * 4 + j];
            #pragma unroll
            for (int i = 0; i < 4; ++i)
                #pragma unroll
                for (int j = 0; j < 4; ++j)
                    acc[i][j] = fmaf(a[i], b[j], acc[i][j]);
        }
    }

    #pragma unroll
    for (int i = 0; i < 4; ++i) {
        int row = m0 + ty * 4 + i;                 // token index [0, 4096)
        int bb = row >> 11;                        // / S
        int s  = row & (S_SZ - 1);
        #pragma unroll
        for (int j = 0; j < 4; ++j) {
            int col = n0 + tx * 4 + j;             // [0, 1024)
            int h = col >> 6;
            int d = col & 63;
            outp[(size_t)((bb * H_SZ + h) * S_SZ + s) * HD_SZ + d] = acc[i][j] + bias[col];
        }
    }
}

// ---------------------------------------------------------------------------
// Pass A: per-row logsumexp stats (m, l) of S = Q K^T / 8, flash-style online.
// Block: one (bh, q-tile of 64). Loops over all k-tiles.
// ---------------------------------------------------------------------------
__global__ __launch_bounds__(256) void attn_lse_kernel() {
    __shared__ float Qs[64][65];
    __shared__ float Ks[64][65];
    const int tid = threadIdx.x;
    const int tx = tid & 15, ty = tid >> 4;
    const int bh = blockIdx.y;
    const int q0 = blockIdx.x * 64;
    const float* Qp = g_Q + (size_t)bh * S_SZ * HD_SZ;
    const float* Kp = g_K + (size_t)bh * S_SZ * HD_SZ;

    #pragma unroll
    for (int i = tid; i < 1024; i += 256) {
        int r = i >> 4, c = (i & 15) << 2;
        float4 v = *(const float4*)(Qp + (size_t)(q0 + r) * HD_SZ + c);
        Qs[r][c] = v.x; Qs[r][c + 1] = v.y; Qs[r][c + 2] = v.z; Qs[r][c + 3] = v.w;
    }

    float m[4], l[4];
    #pragma unroll
    for (int i = 0; i < 4; ++i) { m[i] = -CUDART_INF_F; l[i] = 0.f; }

    for (int k0 = 0; k0 < S_SZ; k0 += 64) {
        __syncthreads();
        #pragma unroll
        for (int i = tid; i < 1024; i += 256) {
            int r = i >> 4, c = (i & 15) << 2;
            float4 v = *(const float4*)(Kp + (size_t)(k0 + r) * HD_SZ + c);
            Ks[r][c] = v.x; Ks[r][c + 1] = v.y; Ks[r][c + 2] = v.z; Ks[r][c + 3] = v.w;
        }
        __syncthreads();

        float acc[4][4] = {};
        #pragma unroll 8
        for (int k = 0; k < 64; ++k) {
            float a[4], b[4];
            #pragma unroll
            for (int i = 0; i < 4; ++i) a[i] = Qs[ty * 4 + i][k];
            #pragma unroll
            for (int j = 0; j < 4; ++j) b[j] = Ks[tx * 4 + j][k];
            #pragma unroll
            for (int i = 0; i < 4; ++i)
                #pragma unroll
                for (int j = 0; j < 4; ++j)
                    acc[i][j] = fmaf(a[i], b[j], acc[i][j]);
        }

        #pragma unroll
        for (int i = 0; i < 4; ++i) {
            float s0 = acc[i][0] * 0.125f;
            float s1 = acc[i][1] * 0.125f;
            float s2 = acc[i][2] * 0.125f;
            float s3 = acc[i][3] * 0.125f;
            float rmax = fmaxf(fmaxf(s0, s1), fmaxf(s2, s3));
            rmax = fmaxf(rmax, __shfl_xor_sync(0xffffffffu, rmax, 1));
            rmax = fmaxf(rmax, __shfl_xor_sync(0xffffffffu, rmax, 2));
            rmax = fmaxf(rmax, __shfl_xor_sync(0xffffffffu, rmax, 4));
            rmax = fmaxf(rmax, __shfl_xor_sync(0xffffffffu, rmax, 8));
            float mn = fmaxf(m[i], rmax);
            float ps = __expf(s0 - mn) + __expf(s1 - mn) + __expf(s2 - mn) + __expf(s3 - mn);
            ps += __shfl_xor_sync(0xffffffffu, ps, 1);
            ps += __shfl_xor_sync(0xffffffffu, ps, 2);
            ps += __shfl_xor_sync(0xffffffffu, ps, 4);
            ps += __shfl_xor_sync(0xffffffffu, ps, 8);
            l[i] = l[i] * __expf(m[i] - mn) + ps;
            m[i] = mn;
        }
    }

    if (tx == 0) {
        #pragma unroll
        for (int i = 0; i < 4; ++i) {
            g_M[bh * S_SZ + q0 + ty * 4 + i] = m[i];
            g_L[bh * S_SZ + q0 + ty * 4 + i] = l[i];
        }
    }
}

// ---------------------------------------------------------------------------
// Pass B: column weights w[k] = (1/S) * sum_q exp(s_qk - m_q) / l_q.
// Block: one (bh, k-tile of 64). Loops over all q-tiles, no atomics.
// ---------------------------------------------------------------------------
__global__ __launch_bounds__(256) void attn_w_kernel() {
    __shared__ float Ks[64][65];
    __shared__ float Qs[64][65];
    __shared__ float msm[64];
    __shared__ float lin[64];
    __shared__ float wred[16][68];
    const int tid = threadIdx.x;
    const int tx = tid & 15, ty = tid >> 4;
    const int bh = blockIdx.y;
    const int k0 = blockIdx.x * 64;
    const float* Qp = g_Q + (size_t)bh * S_SZ * HD_SZ;
    const float* Kp = g_K + (size_t)bh * S_SZ * HD_SZ;

    #pragma unroll
    for (int i = tid; i < 1024; i += 256) {
        int r = i >> 4, c = (i & 15) << 2;
        float4 v = *(const float4*)(Kp + (size_t)(k0 + r) * HD_SZ + c);
        Ks[r][c] = v.x; Ks[r][c + 1] = v.y; Ks[r][c + 2] = v.z; Ks[r][c + 3] = v.w;
    }

    float wacc[4] = {};

    for (int q0 = 0; q0 < S_SZ; q0 += 64) {
        __syncthreads();
        #pragma unroll
        for (int i = tid; i < 1024; i += 256) {
            int r = i >> 4, c = (i & 15) << 2;
            float4 v = *(const float4*)(Qp + (size_t)(q0 + r) * HD_SZ + c);
            Qs[r][c] = v.x; Qs[r][c + 1] = v.y; Qs[r][c + 2] = v.z; Qs[r][c + 3] = v.w;
        }
        if (tid < 64) {
            msm[tid] = g_M[bh * S_SZ + q0 + tid];
            lin[tid] = 1.0f / g_L[bh * S_SZ + q0 + tid];
        }
        __syncthreads();

        float acc[4][4] = {};
        #pragma unroll 8
        for (int k = 0; k < 64; ++k) {
            float a[4], b[4];
            #pragma unroll
            for (int i = 0; i < 4; ++i) a[i] = Qs[ty * 4 + i][k];
            #pragma unroll
            for (int j = 0; j < 4; ++j) b[j] = Ks[tx * 4 + j][k];
            #pragma unroll
            for (int i = 0; i < 4; ++i)
                #pragma unroll
                for (int j = 0; j < 4; ++j)
                    acc[i][j] = fmaf(a[i], b[j], acc[i][j]);
        }

        #pragma unroll
        for (int i = 0; i < 4; ++i) {
            float mi = msm[ty * 4 + i];
            float li = lin[ty * 4 + i];
            #pragma unroll
            for (int j = 0; j < 4; ++j)
                wacc[j] += __expf(fmaf(acc[i][j], 0.125f, -mi)) * li;
        }
    }

    #pragma unroll
    for (int j = 0; j < 4; ++j) wred[ty][tx * 4 + j] = wacc[j];
    __syncthreads();
    if (tid < 64) {
        float sum = 0.f;
        #pragma unroll
        for (int t = 0; t < 16; ++t) sum += wred[t][tid];
        g_w[bh * S_SZ + k0 + tid] = sum * (1.0f / S_SZ);
    }
}

// ---------------------------------------------------------------------------
// Pass C: out[b, h*64+d] = sum_k w[bh,k] * V[bh,k,d]   (w already has 1/S)
// ---------------------------------------------------------------------------
__global__ __launch_bounds__(64) void out_kernel(float* __restrict__ out) {
    const int bh = blockIdx.x;
    const int d = threadIdx.x;
    const float* Vp = g_V + (size_t)bh * S_SZ * HD_SZ;
    const float* wp = g_w + bh * S_SZ;
    float a0 = 0.f, a1 = 0.f, a2 = 0.f, a3 = 0.f;
    for (int k = 0; k < S_SZ; k += 4) {
        a0 = fmaf(wp[k + 0], Vp[(size_t)(k + 0) * HD_SZ + d], a0);
        a1 = fmaf(wp[k + 1], Vp[(size_t)(k + 1) * HD_SZ + d], a1);
        a2 = fmaf(wp[k + 2], Vp[(size_t)(k + 2) * HD_SZ + d], a2);
        a3 = fmaf(wp[k + 3], Vp[(size_t)(k + 3) * HD_SZ + d], a3);
    }
    int bb = bh >> 4, h = bh & 15;
    out[bb * D_SZ + h * HD_SZ + d] = (a0 + a1) + (a2 + a3);
}

// ---------------------------------------------------------------------------
extern "C" void kernel_launch(void* const* d_in, const int* in_sizes, int n_in,
                              void* d_out, int out_size) {
    (void)in_sizes; (void)n_in; (void)out_size;
    const float* X  = (const float*)d_in[0];
    const float* Wq = (const float*)d_in[1];
    const float* bq = (const float*)d_in[2];
    const float* Wk = (const float*)d_in[3];
    const float* bk = (const float*)d_in[4];
    const float* Wv = (const float*)d_in[5];
    const float* bv = (const float*)d_in[6];
    float* out = (float*)d_out;

    dim3 gproj(D_SZ / 64, TOK_SZ / 64);   // (16, 64)
    proj_kernel<<<gproj, 256>>>(X, Wq, bq, 0);
    proj_kernel<<<gproj, 256>>>(X, Wk, bk, 1);
    proj_kernel<<<gproj, 256>>>(X, Wv, bv, 2);

    dim3 ga(S_SZ / 64, BH_SZ);            // (32, 32)
    attn_lse_kernel<<<ga, 256>>>();
    attn_w_kernel<<<ga, 256>>>();

    out_kernel<<<BH_SZ, HD_SZ>>>(out);
}

// round 2
// speedup vs baseline: 3.8459x; 3.8459x over previous
#include <cuda_runtime.h>

#define S_SZ 2048
#define D_SZ 1024
#define H_SZ 16
#define HD_SZ 64
#define B_SZ 2
#define BH_SZ (B_SZ * H_SZ)       // 32
#define TOK_SZ (B_SZ * S_SZ)      // 4096

// Scratch (device globals: allocation-free rule)
__device__ float g_Q[BH_SZ * S_SZ * HD_SZ];
__device__ float g_K[BH_SZ * S_SZ * HD_SZ];
__device__ float g_V[BH_SZ * S_SZ * HD_SZ];
__device__ float g_Ri[BH_SZ * S_SZ];   // 1 / rowsum(exp(scores))
__device__ float g_w[BH_SZ * S_SZ];    // mean attention weight per key

// ---------------------------------------------------------------------------
__device__ __forceinline__ float to_tf32(float x) {
    unsigned u; asm("cvt.rna.tf32.f32 %0, %1;" : "=r"(u) : "f"(x));
    return __uint_as_float(u);
}

__device__ __forceinline__ void mma8(float c[4], const unsigned a[4], const unsigned b[2]) {
    asm volatile(
        "mma.sync.aligned.m16n8k8.row.col.f32.tf32.tf32.f32 "
        "{%0,%1,%2,%3}, {%4,%5,%6,%7}, {%8,%9}, {%0,%1,%2,%3};\n"
        : "+f"(c[0]), "+f"(c[1]), "+f"(c[2]), "+f"(c[3])
        : "r"(a[0]), "r"(a[1]), "r"(a[2]), "r"(a[3]), "r"(b[0]), "r"(b[1]));
}

// exp(s * 0.125) via FMA-only 2^x (no MUFU). Valid for |s*0.125| < ~60.
__device__ __forceinline__ float expsc(float s) {
    const float kk = 0.18033688011112042f;   // 0.125 * log2(e)
    float t = fmaf(s, kk, 12582912.0f);      // round to nearest int (magic)
    int ei = __float_as_int(t) - 0x4B400000; // integer part n
    float r = t - 12582912.0f;               // float(n)
    float f = fmaf(s, kk, -r);               // frac in [-0.5, 0.5]
    float p = 1.33335581e-3f;
    p = fmaf(p, f, 9.61812911e-3f);
    p = fmaf(p, f, 5.55041087e-2f);
    p = fmaf(p, f, 2.40226507e-1f);
    p = fmaf(p, f, 6.93147181e-1f);
    p = fmaf(p, f, 1.0f);
    return __int_as_float(__float_as_int(p) + (ei << 23));  // p * 2^n
}

// ---------------------------------------------------------------------------
// Projection: out[bh,s,d] = X @ W + bias, tf32 mma. Block tile 128x64, K=32 chunks.
// Warps 2(m) x 4(n): warp tile 64x16. 256 threads.
// ---------------------------------------------------------------------------
__global__ __launch_bounds__(256) void proj_mma(const float* __restrict__ X,
                                                const float* __restrict__ W,
                                                const float* __restrict__ bias,
                                                int sel) {
    __shared__ float Xs[128][36];
    __shared__ float Ws[32][72];
    float* outp = (sel == 0) ? g_Q : (sel == 1) ? g_K : g_V;

    const int tid = threadIdx.x, lane = tid & 31, wid = tid >> 5;
    const int wm = wid >> 2, wn = wid & 3;
    const int g = lane >> 2, t = lane & 3;
    const int m0 = blockIdx.y * 128, n0 = blockIdx.x * 64;

    float acc[4][2][4] = {};

    for (int k0 = 0; k0 < D_SZ; k0 += 32) {
        __syncthreads();
        #pragma unroll
        for (int i = tid; i < 1024; i += 256) {
            int r = i >> 3, c = (i & 7) << 2;
            float4 v = *(const float4*)(X + (size_t)(m0 + r) * D_SZ + k0 + c);
            Xs[r][c] = to_tf32(v.x); Xs[r][c + 1] = to_tf32(v.y);
            Xs[r][c + 2] = to_tf32(v.z); Xs[r][c + 3] = to_tf32(v.w);
        }
        #pragma unroll
        for (int i = tid; i < 512; i += 256) {
            int r = i >> 4, c = (i & 15) << 2;
            float4 v = *(const float4*)(W + (size_t)(k0 + r) * D_SZ + n0 + c);
            Ws[r][c] = to_tf32(v.x); Ws[r][c + 1] = to_tf32(v.y);
            Ws[r][c + 2] = to_tf32(v.z); Ws[r][c + 3] = to_tf32(v.w);
        }
        __syncthreads();
        #pragma unroll
        for (int kk = 0; kk < 32; kk += 8) {
            unsigned a[4][4], b[2][2];
            #pragma unroll
            for (int mi = 0; mi < 4; mi++) {
                int rr = wm * 64 + mi * 16;
                a[mi][0] = __float_as_uint(Xs[rr + g][kk + t]);
                a[mi][1] = __float_as_uint(Xs[rr + g + 8][kk + t]);
                a[mi][2] = __float_as_uint(Xs[rr + g][kk + t + 4]);
                a[mi][3] = __float_as_uint(Xs[rr + g + 8][kk + t + 4]);
            }
            #pragma unroll
            for (int nj = 0; nj < 2; nj++) {
                int cc = wn * 16 + nj * 8;
                b[nj][0] = __float_as_uint(Ws[kk + t][cc + g]);
                b[nj][1] = __float_as_uint(Ws[kk + t + 4][cc + g]);
            }
            #pragma unroll
            for (int mi = 0; mi < 4; mi++)
                #pragma unroll
                for (int nj = 0; nj < 2; nj++)
                    mma8(acc[mi][nj], a[mi], b[nj]);
        }
    }

    #pragma unroll
    for (int mi = 0; mi < 4; mi++) {
        int row = m0 + wm * 64 + mi * 16 + g;     // token index
        int bb = row >> 11, s = row & (S_SZ - 1);
        #pragma unroll
        for (int nj = 0; nj < 2; nj++) {
            int col = n0 + wn * 16 + nj * 8 + 2 * t;
            int h = col >> 6, d = col & 63;
            float b0 = bias[col], b1 = bias[col + 1];
            size_t o0 = ((size_t)(bb * H_SZ + h) * S_SZ + s) * HD_SZ + d;
            size_t o2 = ((size_t)(bb * H_SZ + h) * S_SZ + s + 8) * HD_SZ + d;
            outp[o0]     = acc[mi][nj][0] + b0;
            outp[o0 + 1] = acc[mi][nj][1] + b1;
            outp[o2]     = acc[mi][nj][2] + b0;
            outp[o2 + 1] = acc[mi][nj][3] + b1;
        }
    }
}

// ---------------------------------------------------------------------------
// Pass A: per-q-row 1/sum_k exp(qk/8). Block: 128 q rows; stream 128-key chunks.
// Warps 2(m) x 4(n), warp tile 64x32. No max subtraction (scores bounded).
// ---------------------------------------------------------------------------
__global__ __launch_bounds__(256) void lse_mma() {
    extern __shared__ float sm[];
    float (*Qs)[68] = (float(*)[68])sm;                     // 128 x 68
    float (*Ks)[68] = (float(*)[68])(sm + 128 * 68);        // 128 x 68
    float (*red)[128] = (float(*)[128])(sm + 2 * 128 * 68); // 4 x 128

    const int tid = threadIdx.x, lane = tid & 31, wid = tid >> 5;
    const int wm = wid >> 2, wn = wid & 3;
    const int g = lane >> 2, t = lane & 3;
    const int bh = blockIdx.y, q0 = blockIdx.x * 128;
    const float* Qp = g_Q + (size_t)bh * S_SZ * HD_SZ;
    const float* Kp = g_K + (size_t)bh * S_SZ * HD_SZ;

    #pragma unroll
    for (int i = tid; i < 2048; i += 256) {
        int r = i >> 4, c = (i & 15) << 2;
        float4 v = *(const float4*)(Qp + (size_t)(q0 + r) * HD_SZ + c);
        Qs[r][c] = to_tf32(v.x); Qs[r][c + 1] = to_tf32(v.y);
        Qs[r][c + 2] = to_tf32(v.z); Qs[r][c + 3] = to_tf32(v.w);
    }

    float rs[4][2] = {};

    for (int n0 = 0; n0 < S_SZ; n0 += 128) {
        __syncthreads();
        #pragma unroll
        for (int i = tid; i < 2048; i += 256) {
            int r = i >> 4, c = (i & 15) << 2;
            float4 v = *(const float4*)(Kp + (size_t)(n0 + r) * HD_SZ + c);
            Ks[r][c] = to_tf32(v.x); Ks[r][c + 1] = to_tf32(v.y);
            Ks[r][c + 2] = to_tf32(v.z); Ks[r][c + 3] = to_tf32(v.w);
        }
        __syncthreads();

        float acc[4][4][4];
        #pragma unroll
        for (int mi = 0; mi < 4; mi++)
            #pragma unroll
            for (int nj = 0; nj < 4; nj++)
                #pragma unroll
                for (int e = 0; e < 4; e++) acc[mi][nj][e] = 0.f;

        #pragma unroll
        for (int kk = 0; kk < 64; kk += 8) {
            unsigned a[4][4], b[4][2];
            #pragma unroll
            for (int mi = 0; mi < 4; mi++) {
                int rr = wm * 64 + mi * 16;
                a[mi][0] = __float_as_uint(Qs[rr + g][kk + t]);
                a[mi][1] = __float_as_uint(Qs[rr + g + 8][kk + t]);
                a[mi][2] = __float_as_uint(Qs[rr + g][kk + t + 4]);
                a[mi][3] = __float_as_uint(Qs[rr + g + 8][kk + t + 4]);
            }
            #pragma unroll
            for (int nj = 0; nj < 4; nj++) {
                int cc = wn * 32 + nj * 8;
                b[nj][0] = __float_as_uint(Ks[cc + g][kk + t]);
                b[nj][1] = __float_as_uint(Ks[cc + g][kk + t + 4]);
            }
            #pragma unroll
            for (int mi = 0; mi < 4; mi++)
                #pragma unroll
                for (int nj = 0; nj < 4; nj++)
                    mma8(acc[mi][nj], a[mi], b[nj]);
        }

        #pragma unroll
        for (int mi = 0; mi < 4; mi++)
            #pragma unroll
            for (int nj = 0; nj < 4; nj++) {
                rs[mi][0] += expsc(acc[mi][nj][0]) + expsc(acc[mi][nj][1]);
                rs[mi][1] += expsc(acc[mi][nj][2]) + expsc(acc[mi][nj][3]);
            }
    }

    #pragma unroll
    for (int mi = 0; mi < 4; mi++)
        #pragma unroll
        for (int h2 = 0; h2 < 2; h2++) {
            float v = rs[mi][h2];
            v += __shfl_xor_sync(0xffffffffu, v, 1);
            v += __shfl_xor_sync(0xffffffffu, v, 2);
            if (t == 0) red[wn][wm * 64 + mi * 16 + g + 8 * h2] = v;
        }
    __syncthreads();
    if (tid < 128) {
        float l = red[0][tid] + red[1][tid] + red[2][tid] + red[3][tid];
        g_Ri[bh * S_SZ + q0 + tid] = 1.0f / l;
    }
}

// ---------------------------------------------------------------------------
// Pass B: w[k] = (1/S) * sum_q exp(qk/8) * Ri[q]. Block: 128 keys (N); stream
// 128-q chunks (M). Same fragment roles as pass A -> identical score bits.
// ---------------------------------------------------------------------------
__global__ __launch_bounds__(256) void wk_mma() {
    extern __shared__ float sm[];
    float (*Ks)[68] = (float(*)[68])sm;                     // 128 x 68 (resident keys)
    float (*Qs)[68] = (float(*)[68])(sm + 128 * 68);        // 128 x 68 (streamed q)
    float* rsm = sm + 2 * 128 * 68;                          // 128
    float (*wsum)[128] = (float(*)[128])(sm + 2 * 128 * 68 + 128); // 2 x 128

    const int tid = threadIdx.x, lane = tid & 31, wid = tid >> 5;
    const int wm = wid >> 2, wn = wid & 3;
    const int g = lane >> 2, t = lane & 3;
    const int bh = blockIdx.y, k0 = blockIdx.x * 128;
    const float* Qp = g_Q + (size_t)bh * S_SZ * HD_SZ;
    const float* Kp = g_K + (size_t)bh * S_SZ * HD_SZ;

    #pragma unroll
    for (int i = tid; i < 2048; i += 256) {
        int r = i >> 4, c = (i & 15) << 2;
        float4 v = *(const float4*)(Kp + (size_t)(k0 + r) * HD_SZ + c);
        Ks[r][c] = to_tf32(v.x); Ks[r][c + 1] = to_tf32(v.y);
        Ks[r][c + 2] = to_tf32(v.z); Ks[r][c + 3] = to_tf32(v.w);
    }

    float cs[4][2] = {};

    for (int qc = 0; qc < S_SZ; qc += 128) {
        __syncthreads();
        #pragma unroll
        for (int i = tid; i < 2048; i += 256) {
            int r = i >> 4, c = (i & 15) << 2;
            float4 v = *(const float4*)(Qp + (size_t)(qc + r) * HD_SZ + c);
            Qs[r][c] = to_tf32(v.x); Qs[r][c + 1] = to_tf32(v.y);
            Qs[r][c + 2] = to_tf32(v.z); Qs[r][c + 3] = to_tf32(v.w);
        }
        if (tid < 128) rsm[tid] = g_Ri[bh * S_SZ + qc + tid];
        __syncthreads();

        float acc[4][4][4];
        #pragma unroll
        for (int mi = 0; mi < 4; mi++)
            #pragma unroll
            for (int nj = 0; nj < 4; nj++)
                #pragma unroll
                for (int e = 0; e < 4; e++) acc[mi][nj][e] = 0.f;

        #pragma unroll
        for (int kk = 0; kk < 64; kk += 8) {
            unsigned a[4][4], b[4][2];
            #pragma unroll
            for (int mi = 0; mi < 4; mi++) {
                int rr = wm * 64 + mi * 16;
                a[mi][0] = __float_as_uint(Qs[rr + g][kk + t]);
                a[mi][1] = __float_as_uint(Qs[rr + g + 8][kk + t]);
                a[mi][2] = __float_as_uint(Qs[rr + g][kk + t + 4]);
                a[mi][3] = __float_as_uint(Qs[rr + g + 8][kk + t + 4]);
            }
            #pragma unroll
            for (int nj = 0; nj < 4; nj++) {
                int cc = wn * 32 + nj * 8;
                b[nj][0] = __float_as_uint(Ks[cc + g][kk + t]);
                b[nj][1] = __float_as_uint(Ks[cc + g][kk + t + 4]);
            }
            #pragma unroll
            for (int mi = 0; mi < 4; mi++)
                #pragma unroll
                for (int nj = 0; nj < 4; nj++)
                    mma8(acc[mi][nj], a[mi], b[nj]);
        }

        #pragma unroll
        for (int mi = 0; mi < 4; mi++) {
            float r0 = rsm[wm * 64 + mi * 16 + g];
            float r1 = rsm[wm * 64 + mi * 16 + g + 8];
            #pragma unroll
            for (int nj = 0; nj < 4; nj++) {
                cs[nj][0] += expsc(acc[mi][nj][0]) * r0 + expsc(acc[mi][nj][2]) * r1;
                cs[nj][1] += expsc(acc[mi][nj][1]) * r0 + expsc(acc[mi][nj][3]) * r1;
            }
        }
    }

    #pragma unroll
    for (int nj = 0; nj < 4; nj++)
        #pragma unroll
        for (int h2 = 0; h2 < 2; h2++) {
            float v = cs[nj][h2];
            v += __shfl_xor_sync(0xffffffffu, v, 4);
            v += __shfl_xor_sync(0xffffffffu, v, 8);
            v += __shfl_xor_sync(0xffffffffu, v, 16);
            if (g == 0) wsum[wm][wn * 32 + nj * 8 + 2 * t + h2] = v;
        }
    __syncthreads();
    if (tid < 128)
        g_w[bh * S_SZ + k0 + tid] = (wsum[0][tid] + wsum[1][tid]) * (1.0f / S_SZ);
}

// ---------------------------------------------------------------------------
// Output: out[b, h*64+d] = sum_k w[bh,k] * V[bh,k,d]. One block per bh.
// ---------------------------------------------------------------------------
__global__ __launch_bounds__(256) void outk(float* __restrict__ out) {
    __shared__ float red2[4][64];
    const int bh = blockIdx.x, tid = threadIdx.x;
    const int d = tid & 63, sl = tid >> 6;
    const float* Vp = g_V + (size_t)bh * S_SZ * HD_SZ;
    const float* wp = g_w + bh * S_SZ;
    float a = 0.f;
    #pragma unroll 4
    for (int k = sl * 512; k < (sl + 1) * 512; ++k)
        a = fmaf(wp[k], Vp[(size_t)k * HD_SZ + d], a);
    red2[sl][d] = a;
    __syncthreads();
    if (tid < 64) {
        float s = red2[0][tid] + red2[1][tid] + red2[2][tid] + red2[3][tid];
        int bb = bh >> 4, h = bh & 15;
        out[bb * D_SZ + h * HD_SZ + tid] = s;
    }
}

// ---------------------------------------------------------------------------
extern "C" void kernel_launch(void* const* d_in, const int* in_sizes, int n_in,
                              void* d_out, int out_size) {
    (void)in_sizes; (void)n_in; (void)out_size;
    const float* X  = (const float*)d_in[0];
    const float* Wq = (const float*)d_in[1];
    const float* bq = (const float*)d_in[2];
    const float* Wk = (const float*)d_in[3];
    const float* bk = (const float*)d_in[4];
    const float* Wv = (const float*)d_in[5];
    const float* bv = (const float*)d_in[6];
    float* out = (float*)d_out;

    const int lse_smem = (2 * 128 * 68 + 4 * 128) * 4;
    const int wk_smem  = (2 * 128 * 68 + 128 + 2 * 128) * 4;
    cudaFuncSetAttribute(lse_mma, cudaFuncAttributeMaxDynamicSharedMemorySize, lse_smem);
    cudaFuncSetAttribute(wk_mma,  cudaFuncAttributeMaxDynamicSharedMemorySize, wk_smem);

    dim3 gproj(D_SZ / 64, TOK_SZ / 128);     // (16, 32)
    proj_mma<<<gproj, 256>>>(X, Wq, bq, 0);
    proj_mma<<<gproj, 256>>>(X, Wk, bk, 1);
    proj_mma<<<gproj, 256>>>(X, Wv, bv, 2);

    dim3 ga(S_SZ / 128, BH_SZ);              // (16, 32)
    lse_mma<<<ga, 256, lse_smem>>>();
    wk_mma<<<ga, 256, wk_smem>>>();

    outk<<<BH_SZ, 256>>>(out);
}

// round 4
// speedup vs baseline: 4.4812x; 1.1652x over previous
#include <cuda_runtime.h>
#include <cstdint>

#define S_SZ 2048
#define D_SZ 1024
#define H_SZ 16
#define HD_SZ 64
#define B_SZ 2
#define BH_SZ (B_SZ * H_SZ)       // 32
#define TOK_SZ (B_SZ * S_SZ)      // 4096
#define KLOG 0.18033688011112042f // 0.125 * log2(e)

// Scratch (device globals: allocation-free rule)
__device__ float g_Xt[TOK_SZ * D_SZ];        // tf32-rounded X (16MB)
__device__ float g_Wt[3 * D_SZ * D_SZ];      // tf32-rounded Wq,Wk,Wv (12MB)
__device__ float g_Q[BH_SZ * S_SZ * HD_SZ];  // tf32-rounded, pre-scaled by KLOG
__device__ float g_K[BH_SZ * S_SZ * HD_SZ];  // tf32-rounded
__device__ float g_V[BH_SZ * S_SZ * HD_SZ];  // full fp32
__device__ float g_Ri[BH_SZ * S_SZ];         // 1 / rowsum(exp2(scores2))
__device__ float g_w[BH_SZ * S_SZ];          // mean attention weight per key

// ---------------------------------------------------------------------------
__device__ __forceinline__ float to_tf32(float x) {
    unsigned u; asm("cvt.rna.tf32.f32 %0, %1;" : "=r"(u) : "f"(x));
    return __uint_as_float(u);
}

__device__ __forceinline__ void mma8(float c[4], const unsigned a[4], const unsigned b[2]) {
    asm volatile(
        "mma.sync.aligned.m16n8k8.row.col.f32.tf32.tf32.f32 "
        "{%0,%1,%2,%3}, {%4,%5,%6,%7}, {%8,%9}, {%0,%1,%2,%3};\n"
        : "+f"(c[0]), "+f"(c[1]), "+f"(c[2]), "+f"(c[3])
        : "r"(a[0]), "r"(a[1]), "r"(a[2]), "r"(a[3]), "r"(b[0]), "r"(b[1]));
}

// exp2(s), FMA-only. s already in log2 domain (scale folded into Q).
__device__ __forceinline__ float exp2f_fast(float s) {
    float t = s + 12582912.0f;               // round-to-nearest-int magic
    int ei = __float_as_int(t) - 0x4B400000;
    float r = t - 12582912.0f;
    float f = s - r;                         // [-0.5, 0.5]
    float p = 1.33335581e-3f;
    p = fmaf(p, f, 9.61812911e-3f);
    p = fmaf(p, f, 5.55041087e-2f);
    p = fmaf(p, f, 2.40226507e-1f);
    p = fmaf(p, f, 6.93147181e-1f);
    p = fmaf(p, f, 1.0f);
    return __int_as_float(__float_as_int(p) + (ei << 23));
}

__device__ __forceinline__ void cpa16(uint32_t dst, const float* src) {
    asm volatile("cp.async.ca.shared.global [%0], [%1], 16;\n" :: "r"(dst), "l"(src));
}
__device__ __forceinline__ void cp_commit() { asm volatile("cp.async.commit_group;\n"); }
template <int N> __device__ __forceinline__ void cp_wait() {
    asm volatile("cp.async.wait_group %0;\n" :: "n"(N));
}

// ---------------------------------------------------------------------------
// Prep: round X and the three W matrices to tf32 bits.
// ---------------------------------------------------------------------------
__global__ __launch_bounds__(256) void prep_kernel(const float* __restrict__ X,
                                                   const float* __restrict__ Wq,
                                                   const float* __restrict__ Wk,
                                                   const float* __restrict__ Wv) {
    const int NX = TOK_SZ * D_SZ / 4, NW = D_SZ * D_SZ / 4;
    int stride = gridDim.x * blockDim.x;
    for (int i = blockIdx.x * blockDim.x + threadIdx.x; i < NX; i += stride) {
        float4 v = ((const float4*)X)[i];
        v.x = to_tf32(v.x); v.y = to_tf32(v.y); v.z = to_tf32(v.z); v.w = to_tf32(v.w);
        ((float4*)g_Xt)[i] = v;
    }
    for (int w = 0; w < 3; w++) {
        const float* Wp = (w == 0) ? Wq : (w == 1) ? Wk : Wv;
        float4* outp = (float4*)(g_Wt + (size_t)w * D_SZ * D_SZ);
        for (int i = blockIdx.x * blockDim.x + threadIdx.x; i < NW; i += stride) {
            float4 v = ((const float4*)Wp)[i];
            v.x = to_tf32(v.x); v.y = to_tf32(v.y); v.z = to_tf32(v.z); v.w = to_tf32(v.w);
            outp[i] = v;
        }
    }
}

// ---------------------------------------------------------------------------
// Projection: 128x128 tile, K-chunks of 32, cp.async double-buffered.
// Warps 4(m) x 2(n): warp tile 32x64. grid (8, 32, 3).
// ---------------------------------------------------------------------------
#define PROJ_SMEM ((2 * 128 * 36 + 2 * 32 * 136) * 4)
__global__ __launch_bounds__(256) void proj_mma(const float* __restrict__ bq,
                                                const float* __restrict__ bk,
                                                const float* __restrict__ bv) {
    extern __shared__ float sm[];
    float (*Xs)[128][36] = (float(*)[128][36])sm;
    float (*Ws)[32][136] = (float(*)[32][136])(sm + 2 * 128 * 36);

    const int tid = threadIdx.x, lane = tid & 31, wid = tid >> 5;
    const int wm = wid >> 1, wn = wid & 1;
    const int g = lane >> 2, t = lane & 3;
    const int n0 = blockIdx.x * 128, m0 = blockIdx.y * 128, sel = blockIdx.z;
    const float* Xp = g_Xt;
    const float* Wp = g_Wt + (size_t)sel * D_SZ * D_SZ;
    const float* bias = (sel == 0) ? bq : (sel == 1) ? bk : bv;
    float* outp = (sel == 0) ? g_Q : (sel == 1) ? g_K : g_V;

    uint32_t xs_b = (uint32_t)__cvta_generic_to_shared(&Xs[0][0][0]);
    uint32_t ws_b = (uint32_t)__cvta_generic_to_shared(&Ws[0][0][0]);

    auto issue = [&](int ktile, int buf) {
        int k0 = ktile * 32;
        #pragma unroll
        for (int i = tid; i < 1024; i += 256) {   // X tile 128x32
            int r = i >> 3, c = (i & 7) << 2;
            cpa16(xs_b + ((buf * 128 + r) * 36 + c) * 4, Xp + (size_t)(m0 + r) * D_SZ + k0 + c);
        }
        #pragma unroll
        for (int i = tid; i < 1024; i += 256) {   // W tile 32x128
            int r = i >> 5, c = (i & 31) << 2;
            cpa16(ws_b + ((buf * 32 + r) * 136 + c) * 4, Wp + (size_t)(k0 + r) * D_SZ + n0 + c);
        }
        cp_commit();
    };

    float acc[2][8][4] = {};
    issue(0, 0);

    for (int i = 0; i < 32; i++) {
        int buf = i & 1;
        if (i + 1 < 32) { issue(i + 1, 1 - buf); cp_wait<1>(); }
        else cp_wait<0>();
        __syncthreads();

        #pragma unroll
        for (int kk = 0; kk < 32; kk += 8) {
            unsigned a[2][4], b[8][2];
            #pragma unroll
            for (int mi = 0; mi < 2; mi++) {
                int rr = wm * 32 + mi * 16;
                a[mi][0] = __float_as_uint(Xs[buf][rr + g][kk + t]);
                a[mi][1] = __float_as_uint(Xs[buf][rr + g + 8][kk + t]);
                a[mi][2] = __float_as_uint(Xs[buf][rr + g][kk + t + 4]);
                a[mi][3] = __float_as_uint(Xs[buf][rr + g + 8][kk + t + 4]);
            }
            #pragma unroll
            for (int nj = 0; nj < 8; nj++) {
                int cc = wn * 64 + nj * 8;
                b[nj][0] = __float_as_uint(Ws[buf][kk + t][cc + g]);
                b[nj][1] = __float_as_uint(Ws[buf][kk + t + 4][cc + g]);
            }
            #pragma unroll
            for (int mi = 0; mi < 2; mi++)
                #pragma unroll
                for (int nj = 0; nj < 8; nj++)
                    mma8(acc[mi][nj], a[mi], b[nj]);
        }
        __syncthreads();
    }

    #pragma unroll
    for (int mi = 0; mi < 2; mi++) {
        int row = m0 + wm * 32 + mi * 16 + g;
        int bb = row >> 11, s = row & (S_SZ - 1);
        #pragma unroll
        for (int nj = 0; nj < 8; nj++) {
            int col = n0 + wn * 64 + nj * 8 + 2 * t;
            int h = col >> 6, d = col & 63;
            float b0 = bias[col], b1 = bias[col + 1];
            float v0 = acc[mi][nj][0] + b0, v1 = acc[mi][nj][1] + b1;
            float v2 = acc[mi][nj][2] + b0, v3 = acc[mi][nj][3] + b1;
            if (sel == 0) {
                v0 = to_tf32(v0 * KLOG); v1 = to_tf32(v1 * KLOG);
                v2 = to_tf32(v2 * KLOG); v3 = to_tf32(v3 * KLOG);
            } else if (sel == 1) {
                v0 = to_tf32(v0); v1 = to_tf32(v1);
                v2 = to_tf32(v2); v3 = to_tf32(v3);
            }
            size_t o0 = ((size_t)(bb * H_SZ + h) * S_SZ + s) * HD_SZ + d;
            size_t o1 = ((size_t)(bb * H_SZ + h) * S_SZ + s + 8) * HD_SZ + d;
            *(float2*)(outp + o0) = make_float2(v0, v1);
            *(float2*)(outp + o1) = make_float2(v2, v3);
        }
    }
}

// ---------------------------------------------------------------------------
// Pass A (lse): resident A = Q' tile (128 q-rows, pre-scaled), streamed B = K.
// Ri[q] = 1 / sum_k exp2(score2). A-fragments hoisted out of the stream loop.
// ---------------------------------------------------------------------------
#define LSE_SMEM ((128 * 68 + 2 * 128 * 68 + 2 * 128) * 4)
__global__ __launch_bounds__(256) void lse_mma() {
    extern __shared__ float sm[];
    float (*Qs)[68] = (float(*)[68])sm;
    float (*Ks)[128][68] = (float(*)[128][68])(sm + 128 * 68);
    float (*red)[128] = (float(*)[128])(sm + 128 * 68 + 2 * 128 * 68);

    const int tid = threadIdx.x, lane = tid & 31, wid = tid >> 5;
    const int wm = wid >> 1, wn = wid & 1;
    const int g = lane >> 2, t = lane & 3;
    const int bh = blockIdx.y, q0 = blockIdx.x * 128;
    const float* Qp = g_Q + (size_t)bh * S_SZ * HD_SZ;
    const float* Kp = g_K + (size_t)bh * S_SZ * HD_SZ;

    uint32_t qs_b = (uint32_t)__cvta_generic_to_shared(&Qs[0][0]);
    uint32_t ks_b = (uint32_t)__cvta_generic_to_shared(&Ks[0][0][0]);

    // resident Q tile
    #pragma unroll
    for (int i = tid; i < 2048; i += 256) {
        int r = i >> 4, c = (i & 15) << 2;
        cpa16(qs_b + (r * 68 + c) * 4, Qp + (size_t)(q0 + r) * HD_SZ + c);
    }
    cp_commit();

    auto issue = [&](int ktile, int buf) {
        int n0 = ktile * 128;
        #pragma unroll
        for (int i = tid; i < 2048; i += 256) {
            int r = i >> 4, c = (i & 15) << 2;
            cpa16(ks_b + ((buf * 128 + r) * 68 + c) * 4, Kp + (size_t)(n0 + r) * HD_SZ + c);
        }
        cp_commit();
    };

    issue(0, 0);
    cp_wait<0>();
    __syncthreads();

    // hoist resident A fragments (reused across all 16 streamed tiles)
    unsigned afr[8][2][4];
    #pragma unroll
    for (int k8 = 0; k8 < 8; k8++) {
        int kk = k8 * 8;
        #pragma unroll
        for (int mi = 0; mi < 2; mi++) {
            int rr = wm * 32 + mi * 16;
            afr[k8][mi][0] = __float_as_uint(Qs[rr + g][kk + t]);
            afr[k8][mi][1] = __float_as_uint(Qs[rr + g + 8][kk + t]);
            afr[k8][mi][2] = __float_as_uint(Qs[rr + g][kk + t + 4]);
            afr[k8][mi][3] = __float_as_uint(Qs[rr + g + 8][kk + t + 4]);
        }
    }

    float rs[2][2] = {};

    for (int i = 0; i < 16; i++) {
        int buf = i & 1;
        if (i + 1 < 16) { issue(i + 1, 1 - buf); cp_wait<1>(); }
        else cp_wait<0>();
        __syncthreads();

        float acc[2][8][4] = {};
        #pragma unroll
        for (int k8 = 0; k8 < 8; k8++) {
            int kk = k8 * 8;
            unsigned b[8][2];
            #pragma unroll
            for (int nj = 0; nj < 8; nj++) {
                int cc = wn * 64 + nj * 8;
                b[nj][0] = __float_as_uint(Ks[buf][cc + g][kk + t]);
                b[nj][1] = __float_as_uint(Ks[buf][cc + g][kk + t + 4]);
            }
            #pragma unroll
            for (int mi = 0; mi < 2; mi++)
                #pragma unroll
                for (int nj = 0; nj < 8; nj++)
                    mma8(acc[mi][nj], afr[k8][mi], b[nj]);
        }

        #pragma unroll
        for (int mi = 0; mi < 2; mi++)
            #pragma unroll
            for (int nj = 0; nj < 8; nj++) {
                rs[mi][0] += exp2f_fast(acc[mi][nj][0]) + exp2f_fast(acc[mi][nj][1]);
                rs[mi][1] += exp2f_fast(acc[mi][nj][2]) + exp2f_fast(acc[mi][nj][3]);
            }
        __syncthreads();
    }

    #pragma unroll
    for (int mi = 0; mi < 2; mi++)
        #pragma unroll
        for (int h2 = 0; h2 < 2; h2++) {
            float v = rs[mi][h2];
            v += __shfl_xor_sync(0xffffffffu, v, 1);
            v += __shfl_xor_sync(0xffffffffu, v, 2);
            if (t == 0) red[wn][wm * 32 + mi * 16 + g + 8 * h2] = v;
        }
    __syncthreads();
    if (tid < 128)
        g_Ri[bh * S_SZ + q0 + tid] = 1.0f / (red[0][tid] + red[1][tid]);
}

// ---------------------------------------------------------------------------
// Pass B (wk): resident A = K tile (128 keys), streamed B = Q' chunks + Ri.
// w[k] = (1/S) * sum_q exp2(score2) * Ri[q]. Same hoisting as lse.
// ---------------------------------------------------------------------------
#define WK_SMEM ((128 * 68 + 2 * 128 * 68 + 2 * 128 + 2 * 128) * 4)
__global__ __launch_bounds__(256) void wk_mma() {
    extern __shared__ float sm[];
    float (*Kr)[68] = (float(*)[68])sm;
    float (*Qs)[128][68] = (float(*)[128][68])(sm + 128 * 68);
    float (*rsm)[128] = (float(*)[128])(sm + 128 * 68 + 2 * 128 * 68);
    float (*red)[128] = (float(*)[128])(sm + 128 * 68 + 2 * 128 * 68 + 2 * 128);

    const int tid = threadIdx.x, lane = tid & 31, wid = tid >> 5;
    const int wm = wid >> 1, wn = wid & 1;
    const int g = lane >> 2, t = lane & 3;
    const int bh = blockIdx.y, k0 = blockIdx.x * 128;
    const float* Qp = g_Q + (size_t)bh * S_SZ * HD_SZ;
    const float* Kp = g_K + (size_t)bh * S_SZ * HD_SZ;
    const float* Rp = g_Ri + bh * S_SZ;

    uint32_t kr_b = (uint32_t)__cvta_generic_to_shared(&Kr[0][0]);
    uint32_t qs_b = (uint32_t)__cvta_generic_to_shared(&Qs[0][0][0]);
    uint32_t rs_b = (uint32_t)__cvta_generic_to_shared(&rsm[0][0]);

    #pragma unroll
    for (int i = tid; i < 2048; i += 256) {
        int r = i >> 4, c = (i & 15) << 2;
        cpa16(kr_b + (r * 68 + c) * 4, Kp + (size_t)(k0 + r) * HD_SZ + c);
    }
    cp_commit();

    auto issue = [&](int qtile, int buf) {
        int n0 = qtile * 128;
        #pragma unroll
        for (int i = tid; i < 2048; i += 256) {
            int r = i >> 4, c = (i & 15) << 2;
            cpa16(qs_b + ((buf * 128 + r) * 68 + c) * 4, Qp + (size_t)(n0 + r) * HD_SZ + c);
        }
        if (tid < 32) cpa16(rs_b + (buf * 128 + tid * 4) * 4, Rp + n0 + tid * 4);
        cp_commit();
    };

    issue(0, 0);
    cp_wait<0>();
    __syncthreads();

    unsigned afr[8][2][4];
    #pragma unroll
    for (int k8 = 0; k8 < 8; k8++) {
        int kk = k8 * 8;
        #pragma unroll
        for (int mi = 0; mi < 2; mi++) {
            int rr = wm * 32 + mi * 16;
            afr[k8][mi][0] = __float_as_uint(Kr[rr + g][kk + t]);
            afr[k8][mi][1] = __float_as_uint(Kr[rr + g + 8][kk + t]);
            afr[k8][mi][2] = __float_as_uint(Kr[rr + g][kk + t + 4]);
            afr[k8][mi][3] = __float_as_uint(Kr[rr + g + 8][kk + t + 4]);
        }
    }

    float rs[2][2] = {};

    for (int i = 0; i < 16; i++) {
        int buf = i & 1;
        if (i + 1 < 16) { issue(i + 1, 1 - buf); cp_wait<1>(); }
        else cp_wait<0>();
        __syncthreads();

        float acc[2][8][4] = {};
        #pragma unroll
        for (int k8 = 0; k8 < 8; k8++) {
            int kk = k8 * 8;
            unsigned b[8][2];
            #pragma unroll
            for (int nj = 0; nj < 8; nj++) {
                int cc = wn * 64 + nj * 8;
                b[nj][0] = __float_as_uint(Qs[buf][cc + g][kk + t]);
                b[nj][1] = __float_as_uint(Qs[buf][cc + g][kk + t + 4]);
            }
            #pragma unroll
            for (int mi = 0; mi < 2; mi++)
                #pragma unroll
                for (int nj = 0; nj < 8; nj++)
                    mma8(acc[mi][nj], afr[k8][mi], b[nj]);
        }

        #pragma unroll
        for (int nj = 0; nj < 8; nj++) {
            int cb = wn * 64 + nj * 8 + 2 * t;
            float r0 = rsm[buf][cb], r1 = rsm[buf][cb + 1];
            #pragma unroll
            for (int mi = 0; mi < 2; mi++) {
                rs[mi][0] += exp2f_fast(acc[mi][nj][0]) * r0 + exp2f_fast(acc[mi][nj][1]) * r1;
                rs[mi][1] += exp2f_fast(acc[mi][nj][2]) * r0 + exp2f_fast(acc[mi][nj][3]) * r1;
            }
        }
        __syncthreads();
    }

    #pragma unroll
    for (int mi = 0; mi < 2; mi++)
        #pragma unroll
        for (int h2 = 0; h2 < 2; h2++) {
            float v = rs[mi][h2];
            v += __shfl_xor_sync(0xffffffffu, v, 1);
            v += __shfl_xor_sync(0xffffffffu, v, 2);
            if (t == 0) red[wn][wm * 32 + mi * 16 + g + 8 * h2] = v;
        }
    __syncthreads();
    if (tid < 128)
        g_w[bh * S_SZ + k0 + tid] = (red[0][tid] + red[1][tid]) * (1.0f / S_SZ);
}

// ---------------------------------------------------------------------------
// Output: out[b, h*64+d] = sum_k w[bh,k] * V[bh,k,d]. One block per bh.
// ---------------------------------------------------------------------------
__global__ __launch_bounds__(256) void outk(float* __restrict__ out) {
    __shared__ float red2[4][64];
    const int bh = blockIdx.x, tid = threadIdx.x;
    const int d = tid & 63, sl = tid >> 6;
    const float* Vp = g_V + (size_t)bh * S_SZ * HD_SZ;
    const float* wp = g_w + bh * S_SZ;
    float a = 0.f;
    #pragma unroll 4
    for (int k = sl * 512; k < (sl + 1) * 512; ++k)
        a = fmaf(wp[k], Vp[(size_t)k * HD_SZ + d], a);
    red2[sl][d] = a;
    __syncthreads();
    if (tid < 64) {
        float s = red2[0][tid] + red2[1][tid] + red2[2][tid] + red2[3][tid];
        int bb = bh >> 4, h = bh & 15;
        out[bb * D_SZ + h * HD_SZ + tid] = s;
    }
}

// ---------------------------------------------------------------------------
extern "C" void kernel_launch(void* const* d_in, const int* in_sizes, int n_in,
                              void* d_out, int out_size) {
    (void)in_sizes; (void)n_in; (void)out_size;
    const float* X  = (const float*)d_in[0];
    const float* Wq = (const float*)d_in[1];
    const float* bq = (const float*)d_in[2];
    const float* Wk = (const float*)d_in[3];
    const float* bk = (const float*)d_in[4];
    const float* Wv = (const float*)d_in[5];
    const float* bv = (const float*)d_in[6];
    float* out = (float*)d_out;

    cudaFuncSetAttribute(proj_mma, cudaFuncAttributeMaxDynamicSharedMemorySize, PROJ_SMEM);
    cudaFuncSetAttribute(lse_mma,  cudaFuncAttributeMaxDynamicSharedMemorySize, LSE_SMEM);
    cudaFuncSetAttribute(wk_mma,   cudaFuncAttributeMaxDynamicSharedMemorySize, WK_SMEM);

    prep_kernel<<<1024, 256>>>(X, Wq, Wk, Wv);

    dim3 gproj(D_SZ / 128, TOK_SZ / 128, 3);   // (8, 32, 3)
    proj_mma<<<gproj, 256, PROJ_SMEM>>>(bq, bk, bv);

    dim3 ga(S_SZ / 128, BH_SZ);                // (16, 32)
    lse_mma<<<ga, 256, LSE_SMEM>>>();
    wk_mma<<<ga, 256, WK_SMEM>>>();

    outk<<<BH_SZ, 256>>>(out);
}

// round 6
// speedup vs baseline: 4.6222x; 1.0315x over previous
#include <cuda_runtime.h>
#include <cstdint>

#define S_SZ 2048
#define D_SZ 1024
#define H_SZ 16
#define HD_SZ 64
#define B_SZ 2
#define BH_SZ (B_SZ * H_SZ)       // 32
#define TOK_SZ (B_SZ * S_SZ)      // 4096
#define KLOG 0.18033688011112042f // 0.125 * log2(e)

// Scratch (device globals: allocation-free rule)
__device__ float g_Xt[TOK_SZ * D_SZ];        // tf32-rounded X
__device__ float g_Wt[3 * D_SZ * D_SZ];      // tf32-rounded Wq,Wk,Wv
__device__ float g_Q[BH_SZ * S_SZ * HD_SZ];  // tf32-rounded, pre-scaled by KLOG
__device__ float g_K[BH_SZ * S_SZ * HD_SZ];  // tf32-rounded
__device__ float g_V[BH_SZ * S_SZ * HD_SZ];  // full fp32
__device__ float g_Ri[BH_SZ * S_SZ];         // 1 / rowsum(exp2(scores2))
__device__ float g_w[BH_SZ * S_SZ];          // mean attention weight per key

// ---------------------------------------------------------------------------
__device__ __forceinline__ float to_tf32(float x) {
    unsigned u; asm("cvt.rna.tf32.f32 %0, %1;" : "=r"(u) : "f"(x));
    return __uint_as_float(u);
}

__device__ __forceinline__ void mma8(float c[4], const unsigned a[4], const unsigned b[2]) {
    asm volatile(
        "mma.sync.aligned.m16n8k8.row.col.f32.tf32.tf32.f32 "
        "{%0,%1,%2,%3}, {%4,%5,%6,%7}, {%8,%9}, {%0,%1,%2,%3};\n"
        : "+f"(c[0]), "+f"(c[1]), "+f"(c[2]), "+f"(c[3])
        : "r"(a[0]), "r"(a[1]), "r"(a[2]), "r"(a[3]), "r"(b[0]), "r"(b[1]));
}

// exp2(s), FMA-only. s already in log2 domain (scale folded into Q).
__device__ __forceinline__ float exp2f_fast(float s) {
    float t = s + 12582912.0f;               // round-to-nearest-int magic
    int ei = __float_as_int(t) - 0x4B400000;
    float r = t - 12582912.0f;
    float f = s - r;                         // [-0.5, 0.5]
    float p = 1.33335581e-3f;
    p = fmaf(p, f, 9.61812911e-3f);
    p = fmaf(p, f, 5.55041087e-2f);
    p = fmaf(p, f, 2.40226507e-1f);
    p = fmaf(p, f, 6.93147181e-1f);
    p = fmaf(p, f, 1.0f);
    return __int_as_float(__float_as_int(p) + (ei << 23));
}

__device__ __forceinline__ void cpa16(uint32_t dst, const float* src) {
    asm volatile("cp.async.ca.shared.global [%0], [%1], 16;\n" :: "r"(dst), "l"(src));
}
__device__ __forceinline__ void cp_commit() { asm volatile("cp.async.commit_group;\n"); }
template <int N> __device__ __forceinline__ void cp_wait() {
    asm volatile("cp.async.wait_group %0;\n" :: "n"(N));
}

// ---------------------------------------------------------------------------
// Prep: round X and the three W matrices to tf32 bits.
// ---------------------------------------------------------------------------
__global__ __launch_bounds__(256) void prep_kernel(const float* __restrict__ X,
                                                   const float* __restrict__ Wq,
                                                   const float* __restrict__ Wk,
                                                   const float* __restrict__ Wv) {
    const int NX = TOK_SZ * D_SZ / 4, NW = D_SZ * D_SZ / 4;
    int stride = gridDim.x * blockDim.x;
    for (int i = blockIdx.x * blockDim.x + threadIdx.x; i < NX; i += stride) {
        float4 v = ((const float4*)X)[i];
        v.x = to_tf32(v.x); v.y = to_tf32(v.y); v.z = to_tf32(v.z); v.w = to_tf32(v.w);
        ((float4*)g_Xt)[i] = v;
    }
    for (int w = 0; w < 3; w++) {
        const float* Wp = (w == 0) ? Wq : (w == 1) ? Wk : Wv;
        float4* outp = (float4*)(g_Wt + (size_t)w * D_SZ * D_SZ);
        for (int i = blockIdx.x * blockDim.x + threadIdx.x; i < NW; i += stride) {
            float4 v = ((const float4*)Wp)[i];
            v.x = to_tf32(v.x); v.y = to_tf32(v.y); v.z = to_tf32(v.z); v.w = to_tf32(v.w);
            outp[i] = v;
        }
    }
}

// ---------------------------------------------------------------------------
// Projection: 128x128 tile, K-chunks of 32, cp.async double-buffered.
// Warps 4(m) x 2(n): warp tile 32x64. grid (8, 32, 3).
// ---------------------------------------------------------------------------
#define PROJ_SMEM ((2 * 128 * 36 + 2 * 32 * 136) * 4)
__global__ __launch_bounds__(256, 2) void proj_mma(const float* __restrict__ bq,
                                                   const float* __restrict__ bk,
                                                   const float* __restrict__ bv) {
    extern __shared__ float sm[];
    float (*Xs)[128][36] = (float(*)[128][36])sm;
    float (*Ws)[32][136] = (float(*)[32][136])(sm + 2 * 128 * 36);

    const int tid = threadIdx.x, lane = tid & 31, wid = tid >> 5;
    const int wm = wid >> 1, wn = wid & 1;
    const int g = lane >> 2, t = lane & 3;
    const int n0 = blockIdx.x * 128, m0 = blockIdx.y * 128, sel = blockIdx.z;
    const float* Xp = g_Xt;
    const float* Wp = g_Wt + (size_t)sel * D_SZ * D_SZ;
    const float* bias = (sel == 0) ? bq : (sel == 1) ? bk : bv;
    float* outp = (sel == 0) ? g_Q : (sel == 1) ? g_K : g_V;

    uint32_t xs_b = (uint32_t)__cvta_generic_to_shared(&Xs[0][0][0]);
    uint32_t ws_b = (uint32_t)__cvta_generic_to_shared(&Ws[0][0][0]);

    auto issue = [&](int ktile, int buf) {
        int k0 = ktile * 32;
        #pragma unroll
        for (int i = tid; i < 1024; i += 256) {   // X tile 128x32
            int r = i >> 3, c = (i & 7) << 2;
            cpa16(xs_b + ((buf * 128 + r) * 36 + c) * 4, Xp + (size_t)(m0 + r) * D_SZ + k0 + c);
        }
        #pragma unroll
        for (int i = tid; i < 1024; i += 256) {   // W tile 32x128
            int r = i >> 5, c = (i & 31) << 2;
            cpa16(ws_b + ((buf * 32 + r) * 136 + c) * 4, Wp + (size_t)(k0 + r) * D_SZ + n0 + c);
        }
        cp_commit();
    };

    float acc[2][8][4] = {};
    issue(0, 0);

    for (int i = 0; i < 32; i++) {
        int buf = i & 1;
        if (i + 1 < 32) { issue(i + 1, 1 - buf); cp_wait<1>(); }
        else cp_wait<0>();
        __syncthreads();

        #pragma unroll
        for (int kk = 0; kk < 32; kk += 8) {
            unsigned a[2][4], b[8][2];
            #pragma unroll
            for (int mi = 0; mi < 2; mi++) {
                int rr = wm * 32 + mi * 16;
                a[mi][0] = __float_as_uint(Xs[buf][rr + g][kk + t]);
                a[mi][1] = __float_as_uint(Xs[buf][rr + g + 8][kk + t]);
                a[mi][2] = __float_as_uint(Xs[buf][rr + g][kk + t + 4]);
                a[mi][3] = __float_as_uint(Xs[buf][rr + g + 8][kk + t + 4]);
            }
            #pragma unroll
            for (int nj = 0; nj < 8; nj++) {
                int cc = wn * 64 + nj * 8;
                b[nj][0] = __float_as_uint(Ws[buf][kk + t][cc + g]);
                b[nj][1] = __float_as_uint(Ws[buf][kk + t + 4][cc + g]);
            }
            #pragma unroll
            for (int mi = 0; mi < 2; mi++)
                #pragma unroll
                for (int nj = 0; nj < 8; nj++)
                    mma8(acc[mi][nj], a[mi], b[nj]);
        }
        __syncthreads();
    }

    #pragma unroll
    for (int mi = 0; mi < 2; mi++) {
        int row = m0 + wm * 32 + mi * 16 + g;
        int bb = row >> 11, s = row & (S_SZ - 1);
        #pragma unroll
        for (int nj = 0; nj < 8; nj++) {
            int col = n0 + wn * 64 + nj * 8 + 2 * t;
            int h = col >> 6, d = col & 63;
            float b0 = bias[col], b1 = bias[col + 1];
            float v0 = acc[mi][nj][0] + b0, v1 = acc[mi][nj][1] + b1;
            float v2 = acc[mi][nj][2] + b0, v3 = acc[mi][nj][3] + b1;
            if (sel == 0) {
                v0 = to_tf32(v0 * KLOG); v1 = to_tf32(v1 * KLOG);
                v2 = to_tf32(v2 * KLOG); v3 = to_tf32(v3 * KLOG);
            } else if (sel == 1) {
                v0 = to_tf32(v0); v1 = to_tf32(v1);
                v2 = to_tf32(v2); v3 = to_tf32(v3);
            }
            size_t o0 = ((size_t)(bb * H_SZ + h) * S_SZ + s) * HD_SZ + d;
            size_t o1 = ((size_t)(bb * H_SZ + h) * S_SZ + s + 8) * HD_SZ + d;
            *(float2*)(outp + o0) = make_float2(v0, v1);
            *(float2*)(outp + o1) = make_float2(v2, v3);
        }
    }
}

// ---------------------------------------------------------------------------
// Pass A (lse): resident A = Q' tile (128 q-rows, pre-scaled), streamed B = K.
// Ri[q] = 1 / sum_k exp2(score2). A-frags loaded in-loop (occupancy > hoist).
// ---------------------------------------------------------------------------
#define LSE_SMEM ((128 * 68 + 2 * 128 * 68 + 2 * 128) * 4)
__global__ __launch_bounds__(256, 2) void lse_mma() {
    extern __shared__ float sm[];
    float (*Qs)[68] = (float(*)[68])sm;
    float (*Ks)[128][68] = (float(*)[128][68])(sm + 128 * 68);
    float (*red)[128] = (float(*)[128])(sm + 128 * 68 + 2 * 128 * 68);

    const int tid = threadIdx.x, lane = tid & 31, wid = tid >> 5;
    const int wm = wid >> 1, wn = wid & 1;
    const int g = lane >> 2, t = lane & 3;
    const int bh = blockIdx.y, q0 = blockIdx.x * 128;
    const float* Qp = g_Q + (size_t)bh * S_SZ * HD_SZ;
    const float* Kp = g_K + (size_t)bh * S_SZ * HD_SZ;

    uint32_t qs_b = (uint32_t)__cvta_generic_to_shared(&Qs[0][0]);
    uint32_t ks_b = (uint32_t)__cvta_generic_to_shared(&Ks[0][0][0]);

    #pragma unroll
    for (int i = tid; i < 2048; i += 256) {
        int r = i >> 4, c = (i & 15) << 2;
        cpa16(qs_b + (r * 68 + c) * 4, Qp + (size_t)(q0 + r) * HD_SZ + c);
    }
    cp_commit();

    auto issue = [&](int ktile, int buf) {
        int n0 = ktile * 128;
        #pragma unroll
        for (int i = tid; i < 2048; i += 256) {
            int r = i >> 4, c = (i & 15) << 2;
            cpa16(ks_b + ((buf * 128 + r) * 68 + c) * 4, Kp + (size_t)(n0 + r) * HD_SZ + c);
        }
        cp_commit();
    };

    issue(0, 0);
    cp_wait<0>();
    __syncthreads();

    float rs[2][2] = {};

    for (int i = 0; i < 16; i++) {
        int buf = i & 1;
        if (i + 1 < 16) { issue(i + 1, 1 - buf); cp_wait<1>(); }
        else cp_wait<0>();
        __syncthreads();

        float acc[2][8][4] = {};
        #pragma unroll
        for (int k8 = 0; k8 < 8; k8++) {
            int kk = k8 * 8;
            unsigned a[2][4], b[8][2];
            #pragma unroll
            for (int mi = 0; mi < 2; mi++) {
                int rr = wm * 32 + mi * 16;
                a[mi][0] = __float_as_uint(Qs[rr + g][kk + t]);
                a[mi][1] = __float_as_uint(Qs[rr + g + 8][kk + t]);
                a[mi][2] = __float_as_uint(Qs[rr + g][kk + t + 4]);
                a[mi][3] = __float_as_uint(Qs[rr + g + 8][kk + t + 4]);
            }
            #pragma unroll
            for (int nj = 0; nj < 8; nj++) {
                int cc = wn * 64 + nj * 8;
                b[nj][0] = __float_as_uint(Ks[buf][cc + g][kk + t]);
                b[nj][1] = __float_as_uint(Ks[buf][cc + g][kk + t + 4]);
            }
            #pragma unroll
            for (int mi = 0; mi < 2; mi++)
                #pragma unroll
                for (int nj = 0; nj < 8; nj++)
                    mma8(acc[mi][nj], a[mi], b[nj]);
        }

        #pragma unroll
        for (int mi = 0; mi < 2; mi++)
            #pragma unroll
            for (int nj = 0; nj < 8; nj++) {
                rs[mi][0] += exp2f_fast(acc[mi][nj][0]) + exp2f_fast(acc[mi][nj][1]);
                rs[mi][1] += exp2f_fast(acc[mi][nj][2]) + exp2f_fast(acc[mi][nj][3]);
            }
        __syncthreads();
    }

    #pragma unroll
    for (int mi = 0; mi < 2; mi++)
        #pragma unroll
        for (int h2 = 0; h2 < 2; h2++) {
            float v = rs[mi][h2];
            v += __shfl_xor_sync(0xffffffffu, v, 1);
            v += __shfl_xor_sync(0xffffffffu, v, 2);
            if (t == 0) red[wn][wm * 32 + mi * 16 + g + 8 * h2] = v;
        }
    __syncthreads();
    if (tid < 128)
        g_Ri[bh * S_SZ + q0 + tid] = 1.0f / (red[0][tid] + red[1][tid]);
}

// ---------------------------------------------------------------------------
// Pass B (wk): resident A = K tile (128 keys), streamed B = Q' chunks + Ri.
// w[k] = (1/S) * sum_q exp2(score2) * Ri[q].
// ---------------------------------------------------------------------------
#define WK_SMEM ((128 * 68 + 2 * 128 * 68 + 2 * 128 + 2 * 128) * 4)
__global__ __launch_bounds__(256, 2) void wk_mma() {
    extern __shared__ float sm[];
    float (*Kr)[68] = (float(*)[68])sm;
    float (*Qs)[128][68] = (float(*)[128][68])(sm + 128 * 68);
    float (*rsm)[128] = (float(*)[128])(sm + 128 * 68 + 2 * 128 * 68);
    float (*red)[128] = (float(*)[128])(sm + 128 * 68 + 2 * 128 * 68 + 2 * 128);

    const int tid = threadIdx.x, lane = tid & 31, wid = tid >> 5;
    const int wm = wid >> 1, wn = wid & 1;
    const int g = lane >> 2, t = lane & 3;
    const int bh = blockIdx.y, k0 = blockIdx.x * 128;
    const float* Qp = g_Q + (size_t)bh * S_SZ * HD_SZ;
    const float* Kp = g_K + (size_t)bh * S_SZ * HD_SZ;
    const float* Rp = g_Ri + bh * S_SZ;

    uint32_t kr_b = (uint32_t)__cvta_generic_to_shared(&Kr[0][0]);
    uint32_t qs_b = (uint32_t)__cvta_generic_to_shared(&Qs[0][0][0]);
    uint32_t rs_b = (uint32_t)__cvta_generic_to_shared(&rsm[0][0]);

    #pragma unroll
    for (int i = tid; i < 2048; i += 256) {
        int r = i >> 4, c = (i & 15) << 2;
        cpa16(kr_b + (r * 68 + c) * 4, Kp + (size_t)(k0 + r) * HD_SZ + c);
    }
    cp_commit();

    auto issue = [&](int qtile, int buf) {
        int n0 = qtile * 128;
        #pragma unroll
        for (int i = tid; i < 2048; i += 256) {
            int r = i >> 4, c = (i & 15) << 2;
            cpa16(qs_b + ((buf * 128 + r) * 68 + c) * 4, Qp + (size_t)(n0 + r) * HD_SZ + c);
        }
        if (tid < 32) cpa16(rs_b + (buf * 128 + tid * 4) * 4, Rp + n0 + tid * 4);
        cp_commit();
    };

    issue(0, 0);
    cp_wait<0>();
    __syncthreads();

    float rs[2][2] = {};

    for (int i = 0; i < 16; i++) {
        int buf = i & 1;
        if (i + 1 < 16) { issue(i + 1, 1 - buf); cp_wait<1>(); }
        else cp_wait<0>();
        __syncthreads();

        float acc[2][8][4] = {};
        #pragma unroll
        for (int k8 = 0; k8 < 8; k8++) {
            int kk = k8 * 8;
            unsigned a[2][4], b[8][2];
            #pragma unroll
            for (int mi = 0; mi < 2; mi++) {
                int rr = wm * 32 + mi * 16;
                a[mi][0] = __float_as_uint(Kr[rr + g][kk + t]);
                a[mi][1] = __float_as_uint(Kr[rr + g + 8][kk + t]);
                a[mi][2] = __float_as_uint(Kr[rr + g][kk + t + 4]);
                a[mi][3] = __float_as_uint(Kr[rr + g + 8][kk + t + 4]);
            }
            #pragma unroll
            for (int nj = 0; nj < 8; nj++) {
                int cc = wn * 64 + nj * 8;
                b[nj][0] = __float_as_uint(Qs[buf][cc + g][kk + t]);
                b[nj][1] = __float_as_uint(Qs[buf][cc + g][kk + t + 4]);
            }
            #pragma unroll
            for (int mi = 0; mi < 2; mi++)
                #pragma unroll
                for (int nj = 0; nj < 8; nj++)
                    mma8(acc[mi][nj], a[mi], b[nj]);
        }

        #pragma unroll
        for (int nj = 0; nj < 8; nj++) {
            int cb = wn * 64 + nj * 8 + 2 * t;
            float r0 = rsm[buf][cb], r1 = rsm[buf][cb + 1];
            #pragma unroll
            for (int mi = 0; mi < 2; mi++) {
                rs[mi][0] += exp2f_fast(acc[mi][nj][0]) * r0 + exp2f_fast(acc[mi][nj][1]) * r1;
                rs[mi][1] += exp2f_fast(acc[mi][nj][2]) * r0 + exp2f_fast(acc[mi][nj][3]) * r1;
            }
        }
        __syncthreads();
    }

    #pragma unroll
    for (int mi = 0; mi < 2; mi++)
        #pragma unroll
        for (int h2 = 0; h2 < 2; h2++) {
            float v = rs[mi][h2];
            v += __shfl_xor_sync(0xffffffffu, v, 1);
            v += __shfl_xor_sync(0xffffffffu, v, 2);
            if (t == 0) red[wn][wm * 32 + mi * 16 + g + 8 * h2] = v;
        }
    __syncthreads();
    if (tid < 128)
        g_w[bh * S_SZ + k0 + tid] = (red[0][tid] + red[1][tid]) * (1.0f / S_SZ);
}

// ---------------------------------------------------------------------------
// Output: out[b, h*64+d] = sum_k w[bh,k] * V[bh,k,d]. One block per bh.
// ---------------------------------------------------------------------------
__global__ __launch_bounds__(256) void outk(float* __restrict__ out) {
    __shared__ float red2[4][64];
    const int bh = blockIdx.x, tid = threadIdx.x;
    const int d = tid & 63, sl = tid >> 6;
    const float* Vp = g_V + (size_t)bh * S_SZ * HD_SZ;
    const float* wp = g_w + bh * S_SZ;
    float a = 0.f;
    #pragma unroll 4
    for (int k = sl * 512; k < (sl + 1) * 512; ++k)
        a = fmaf(wp[k], Vp[(size_t)k * HD_SZ + d], a);
    red2[sl][d] = a;
    __syncthreads();
    if (tid < 64) {
        float s = red2[0][tid] + red2[1][tid] + red2[2][tid] + red2[3][tid];
        int bb = bh >> 4, h = bh & 15;
        out[bb * D_SZ + h * HD_SZ + tid] = s;
    }
}

// ---------------------------------------------------------------------------
extern "C" void kernel_launch(void* const* d_in, const int* in_sizes, int n_in,
                              void* d_out, int out_size) {
    (void)in_sizes; (void)n_in; (void)out_size;
    const float* X  = (const float*)d_in[0];
    const float* Wq = (const float*)d_in[1];
    const float* bq = (const float*)d_in[2];
    const float* Wk = (const float*)d_in[3];
    const float* bk = (const float*)d_in[4];
    const float* Wv = (const float*)d_in[5];
    const float* bv = (const float*)d_in[6];
    float* out = (float*)d_out;

    cudaFuncSetAttribute(proj_mma, cudaFuncAttributeMaxDynamicSharedMemorySize, PROJ_SMEM);
    cudaFuncSetAttribute(lse_mma,  cudaFuncAttributeMaxDynamicSharedMemorySize, LSE_SMEM);
    cudaFuncSetAttribute(wk_mma,   cudaFuncAttributeMaxDynamicSharedMemorySize, WK_SMEM);

    prep_kernel<<<1024, 256>>>(X, Wq, Wk, Wv);

    dim3 gproj(D_SZ / 128, TOK_SZ / 128, 3);   // (8, 32, 3)
    proj_mma<<<gproj, 256, PROJ_SMEM>>>(bq, bk, bv);

    dim3 ga(S_SZ / 128, BH_SZ);                // (16, 32)
    lse_mma<<<ga, 256, LSE_SMEM>>>();
    wk_mma<<<ga, 256, WK_SMEM>>>();

    outk<<<BH_SZ, 256>>>(out);
}

// round 7
// speedup vs baseline: 4.8263x; 1.0442x over previous
#include <cuda_runtime.h>
#include <cstdint>

#define S_SZ 2048
#define D_SZ 1024
#define H_SZ 16
#define HD_SZ 64
#define B_SZ 2
#define BH_SZ (B_SZ * H_SZ)       // 32
#define TOK_SZ (B_SZ * S_SZ)      // 4096
#define KLOG 0.18033688011112042f // 0.125 * log2(e)

// Scratch (device globals: allocation-free rule)
__device__ float g_Xt[TOK_SZ * D_SZ];        // tf32-rounded X
__device__ float g_Wt[3 * D_SZ * D_SZ];      // tf32-rounded Wq,Wk,Wv
__device__ float g_Q[BH_SZ * S_SZ * HD_SZ];  // tf32, KLOG-scaled, octet-permuted d
__device__ float g_K[BH_SZ * S_SZ * HD_SZ];  // tf32, octet-permuted d
__device__ float g_V[BH_SZ * S_SZ * HD_SZ];  // full fp32
__device__ float g_Ri[BH_SZ * S_SZ];         // 1 / rowsum(exp2(scores2))
__device__ float g_w[BH_SZ * S_SZ];          // mean attention weight per key

// ---------------------------------------------------------------------------
__device__ __forceinline__ float to_tf32(float x) {
    unsigned u; asm("cvt.rna.tf32.f32 %0, %1;" : "=r"(u) : "f"(x));
    return __uint_as_float(u);
}

__device__ __forceinline__ void mma8(float c[4], const unsigned a[4], const unsigned b[2]) {
    asm volatile(
        "mma.sync.aligned.m16n8k8.row.col.f32.tf32.tf32.f32 "
        "{%0,%1,%2,%3}, {%4,%5,%6,%7}, {%8,%9}, {%0,%1,%2,%3};\n"
        : "+f"(c[0]), "+f"(c[1]), "+f"(c[2]), "+f"(c[3])
        : "r"(a[0]), "r"(a[1]), "r"(a[2]), "r"(a[3]), "r"(b[0]), "r"(b[1]));
}

// 2^x on the MUFU pipe (input already in log2 domain).
__device__ __forceinline__ float ex2(float x) {
    float y; asm("ex2.approx.f32 %0, %1;" : "=f"(y) : "f"(x)); return y;
}

__device__ __forceinline__ void cpa16(uint32_t dst, const float* src) {
    asm volatile("cp.async.ca.shared.global [%0], [%1], 16;\n" :: "r"(dst), "l"(src));
}
__device__ __forceinline__ void cp_commit() { asm volatile("cp.async.commit_group;\n"); }
template <int N> __device__ __forceinline__ void cp_wait() {
    asm volatile("cp.async.wait_group %0;\n" :: "n"(N));
}

// ---------------------------------------------------------------------------
// Prep: round X and the three W matrices to tf32 bits.
// ---------------------------------------------------------------------------
__global__ __launch_bounds__(256) void prep_kernel(const float* __restrict__ X,
                                                   const float* __restrict__ Wq,
                                                   const float* __restrict__ Wk,
                                                   const float* __restrict__ Wv) {
    const int NX = TOK_SZ * D_SZ / 4, NW = D_SZ * D_SZ / 4;
    int stride = gridDim.x * blockDim.x;
    for (int i = blockIdx.x * blockDim.x + threadIdx.x; i < NX; i += stride) {
        float4 v = ((const float4*)X)[i];
        v.x = to_tf32(v.x); v.y = to_tf32(v.y); v.z = to_tf32(v.z); v.w = to_tf32(v.w);
        ((float4*)g_Xt)[i] = v;
    }
    for (int w = 0; w < 3; w++) {
        const float* Wp = (w == 0) ? Wq : (w == 1) ? Wk : Wv;
        float4* outp = (float4*)(g_Wt + (size_t)w * D_SZ * D_SZ);
        for (int i = blockIdx.x * blockDim.x + threadIdx.x; i < NW; i += stride) {
            float4 v = ((const float4*)Wp)[i];
            v.x = to_tf32(v.x); v.y = to_tf32(v.y); v.z = to_tf32(v.z); v.w = to_tf32(v.w);
            outp[i] = v;
        }
    }
}

// ---------------------------------------------------------------------------
// Projection: 128x128 tile, K-chunks of 32, cp.async double-buffered.
// Q/K epilogue applies the octet permutation p(c)=2(c&3)+(c>>2) within each
// 8-wide d-group so attention fragment loads can be float2.
// ---------------------------------------------------------------------------
#define PROJ_SMEM ((2 * 128 * 36 + 2 * 32 * 136) * 4)
__global__ __launch_bounds__(256, 2) void proj_mma(const float* __restrict__ bq,
                                                   const float* __restrict__ bk,
                                                   const float* __restrict__ bv) {
    extern __shared__ float sm[];
    float (*Xs)[128][36] = (float(*)[128][36])sm;
    float (*Ws)[32][136] = (float(*)[32][136])(sm + 2 * 128 * 36);

    const int tid = threadIdx.x, lane = tid & 31, wid = tid >> 5;
    const int wm = wid >> 1, wn = wid & 1;
    const int g = lane >> 2, t = lane & 3;
    const int n0 = blockIdx.x * 128, m0 = blockIdx.y * 128, sel = blockIdx.z;
    const float* Xp = g_Xt;
    const float* Wp = g_Wt + (size_t)sel * D_SZ * D_SZ;
    const float* bias = (sel == 0) ? bq : (sel == 1) ? bk : bv;
    float* outp = (sel == 0) ? g_Q : (sel == 1) ? g_K : g_V;

    uint32_t xs_b = (uint32_t)__cvta_generic_to_shared(&Xs[0][0][0]);
    uint32_t ws_b = (uint32_t)__cvta_generic_to_shared(&Ws[0][0][0]);

    auto issue = [&](int ktile, int buf) {
        int k0 = ktile * 32;
        #pragma unroll
        for (int i = tid; i < 1024; i += 256) {   // X tile 128x32
            int r = i >> 3, c = (i & 7) << 2;
            cpa16(xs_b + ((buf * 128 + r) * 36 + c) * 4, Xp + (size_t)(m0 + r) * D_SZ + k0 + c);
        }
        #pragma unroll
        for (int i = tid; i < 1024; i += 256) {   // W tile 32x128
            int r = i >> 5, c = (i & 31) << 2;
            cpa16(ws_b + ((buf * 32 + r) * 136 + c) * 4, Wp + (size_t)(k0 + r) * D_SZ + n0 + c);
        }
        cp_commit();
    };

    float acc[2][8][4] = {};
    issue(0, 0);

    for (int i = 0; i < 32; i++) {
        int buf = i & 1;
        if (i + 1 < 32) { issue(i + 1, 1 - buf); cp_wait<1>(); }
        else cp_wait<0>();
        __syncthreads();

        #pragma unroll
        for (int kk = 0; kk < 32; kk += 8) {
            unsigned a[2][4], b[8][2];
            #pragma unroll
            for (int mi = 0; mi < 2; mi++) {
                int rr = wm * 32 + mi * 16;
                a[mi][0] = __float_as_uint(Xs[buf][rr + g][kk + t]);
                a[mi][1] = __float_as_uint(Xs[buf][rr + g + 8][kk + t]);
                a[mi][2] = __float_as_uint(Xs[buf][rr + g][kk + t + 4]);
                a[mi][3] = __float_as_uint(Xs[buf][rr + g + 8][kk + t + 4]);
            }
            #pragma unroll
            for (int nj = 0; nj < 8; nj++) {
                int cc = wn * 64 + nj * 8;
                b[nj][0] = __float_as_uint(Ws[buf][kk + t][cc + g]);
                b[nj][1] = __float_as_uint(Ws[buf][kk + t + 4][cc + g]);
            }
            #pragma unroll
            for (int mi = 0; mi < 2; mi++)
                #pragma unroll
                for (int nj = 0; nj < 8; nj++)
                    mma8(acc[mi][nj], a[mi], b[nj]);
        }
        __syncthreads();
    }

    #pragma unroll
    for (int mi = 0; mi < 2; mi++) {
        int row = m0 + wm * 32 + mi * 16 + g;
        int bb = row >> 11, s = row & (S_SZ - 1);
        #pragma unroll
        for (int nj = 0; nj < 8; nj++) {
            int col = n0 + wn * 64 + nj * 8 + 2 * t;
            int h = col >> 6, d = col & 63;
            float b0 = bias[col], b1 = bias[col + 1];
            float v0 = acc[mi][nj][0] + b0, v1 = acc[mi][nj][1] + b1;
            float v2 = acc[mi][nj][2] + b0, v3 = acc[mi][nj][3] + b1;
            size_t base0 = ((size_t)(bb * H_SZ + h) * S_SZ + s) * HD_SZ;
            size_t base1 = ((size_t)(bb * H_SZ + h) * S_SZ + s + 8) * HD_SZ;
            if (sel == 2) {
                *(float2*)(outp + base0 + d) = make_float2(v0, v1);
                *(float2*)(outp + base1 + d) = make_float2(v2, v3);
            } else {
                if (sel == 0) {
                    v0 = to_tf32(v0 * KLOG); v1 = to_tf32(v1 * KLOG);
                    v2 = to_tf32(v2 * KLOG); v3 = to_tf32(v3 * KLOG);
                } else {
                    v0 = to_tf32(v0); v1 = to_tf32(v1);
                    v2 = to_tf32(v2); v3 = to_tf32(v3);
                }
                int oct = d >> 3, w0 = d & 7, w1 = w0 + 1;
                int p0 = (oct << 3) + ((w0 & 3) << 1) + (w0 >> 2);
                int p1 = (oct << 3) + ((w1 & 3) << 1) + (w1 >> 2);
                outp[base0 + p0] = v0; outp[base0 + p1] = v1;
                outp[base1 + p0] = v2; outp[base1 + p1] = v3;
            }
        }
    }
}

// ---------------------------------------------------------------------------
// Pass A (lse): resident A = Q' (128 q-rows), streamed B = K. Stride 72,
// octet-permuted k-layout -> all fragment loads are conflict-free LDS.64.
// ---------------------------------------------------------------------------
#define LSE_SMEM ((128 * 72 + 2 * 128 * 72 + 2 * 128) * 4)
__global__ __launch_bounds__(256, 2) void lse_mma() {
    extern __shared__ float sm[];
    float (*Qs)[72] = (float(*)[72])sm;
    float (*Ks)[128][72] = (float(*)[128][72])(sm + 128 * 72);
    float (*red)[128] = (float(*)[128])(sm + 128 * 72 + 2 * 128 * 72);

    const int tid = threadIdx.x, lane = tid & 31, wid = tid >> 5;
    const int wm = wid >> 1, wn = wid & 1;
    const int g = lane >> 2, t = lane & 3;
    const int bh = blockIdx.y, q0 = blockIdx.x * 128;
    const float* Qp = g_Q + (size_t)bh * S_SZ * HD_SZ;
    const float* Kp = g_K + (size_t)bh * S_SZ * HD_SZ;

    uint32_t qs_b = (uint32_t)__cvta_generic_to_shared(&Qs[0][0]);
    uint32_t ks_b = (uint32_t)__cvta_generic_to_shared(&Ks[0][0][0]);

    #pragma unroll
    for (int i = tid; i < 2048; i += 256) {
        int r = i >> 4, c = (i & 15) << 2;
        cpa16(qs_b + (r * 72 + c) * 4, Qp + (size_t)(q0 + r) * HD_SZ + c);
    }
    cp_commit();

    auto issue = [&](int ktile, int buf) {
        int n0 = ktile * 128;
        #pragma unroll
        for (int i = tid; i < 2048; i += 256) {
            int r = i >> 4, c = (i & 15) << 2;
            cpa16(ks_b + ((buf * 128 + r) * 72 + c) * 4, Kp + (size_t)(n0 + r) * HD_SZ + c);
        }
        cp_commit();
    };

    issue(0, 0);
    cp_wait<0>();
    __syncthreads();

    float rs[2][2] = {};

    for (int i = 0; i < 16; i++) {
        int buf = i & 1;
        if (i + 1 < 16) { issue(i + 1, 1 - buf); cp_wait<1>(); }
        else cp_wait<0>();
        __syncthreads();

        float acc[2][8][4] = {};
        #pragma unroll
        for (int k8 = 0; k8 < 8; k8++) {
            int kk = k8 * 8;
            unsigned a[2][4], b[8][2];
            #pragma unroll
            for (int mi = 0; mi < 2; mi++) {
                int rr = wm * 32 + mi * 16;
                float2 fa0 = ((const float2*)&Qs[rr + g][kk])[t];
                float2 fa1 = ((const float2*)&Qs[rr + g + 8][kk])[t];
                a[mi][0] = __float_as_uint(fa0.x); a[mi][2] = __float_as_uint(fa0.y);
                a[mi][1] = __float_as_uint(fa1.x); a[mi][3] = __float_as_uint(fa1.y);
            }
            #pragma unroll
            for (int nj = 0; nj < 8; nj++) {
                int cc = wn * 64 + nj * 8;
                float2 fb = ((const float2*)&Ks[buf][cc + g][kk])[t];
                b[nj][0] = __float_as_uint(fb.x); b[nj][1] = __float_as_uint(fb.y);
            }
            #pragma unroll
            for (int mi = 0; mi < 2; mi++)
                #pragma unroll
                for (int nj = 0; nj < 8; nj++)
                    mma8(acc[mi][nj], a[mi], b[nj]);
        }

        #pragma unroll
        for (int mi = 0; mi < 2; mi++)
            #pragma unroll
            for (int nj = 0; nj < 8; nj++) {
                rs[mi][0] += ex2(acc[mi][nj][0]) + ex2(acc[mi][nj][1]);
                rs[mi][1] += ex2(acc[mi][nj][2]) + ex2(acc[mi][nj][3]);
            }
        __syncthreads();
    }

    #pragma unroll
    for (int mi = 0; mi < 2; mi++)
        #pragma unroll
        for (int h2 = 0; h2 < 2; h2++) {
            float v = rs[mi][h2];
            v += __shfl_xor_sync(0xffffffffu, v, 1);
            v += __shfl_xor_sync(0xffffffffu, v, 2);
            if (t == 0) red[wn][wm * 32 + mi * 16 + g + 8 * h2] = v;
        }
    __syncthreads();
    if (tid < 128)
        g_Ri[bh * S_SZ + q0 + tid] = 1.0f / (red[0][tid] + red[1][tid]);
}

// ---------------------------------------------------------------------------
// Pass B (wk): resident A = K (128 keys), streamed B = Q' + Ri.
// w[k] = (1/S) * sum_q exp2(score2) * Ri[q].
// ---------------------------------------------------------------------------
#define WK_SMEM ((128 * 72 + 2 * 128 * 72 + 2 * 128 + 2 * 128) * 4)
__global__ __launch_bounds__(256, 2) void wk_mma() {
    extern __shared__ float sm[];
    float (*Kr)[72] = (float(*)[72])sm;
    float (*Qs)[128][72] = (float(*)[128][72])(sm + 128 * 72);
    float (*rsm)[128] = (float(*)[128])(sm + 128 * 72 + 2 * 128 * 72);
    float (*red)[128] = (float(*)[128])(sm + 128 * 72 + 2 * 128 * 72 + 2 * 128);

    const int tid = threadIdx.x, lane = tid & 31, wid = tid >> 5;
    const int wm = wid >> 1, wn = wid & 1;
    const int g = lane >> 2, t = lane & 3;
    const int bh = blockIdx.y, k0 = blockIdx.x * 128;
    const float* Qp = g_Q + (size_t)bh * S_SZ * HD_SZ;
    const float* Kp = g_K + (size_t)bh * S_SZ * HD_SZ;
    const float* Rp = g_Ri + bh * S_SZ;

    uint32_t kr_b = (uint32_t)__cvta_generic_to_shared(&Kr[0][0]);
    uint32_t qs_b = (uint32_t)__cvta_generic_to_shared(&Qs[0][0][0]);
    uint32_t rs_b = (uint32_t)__cvta_generic_to_shared(&rsm[0][0]);

    #pragma unroll
    for (int i = tid; i < 2048; i += 256) {
        int r = i >> 4, c = (i & 15) << 2;
        cpa16(kr_b + (r * 72 + c) * 4, Kp + (size_t)(k0 + r) * HD_SZ + c);
    }
    cp_commit();

    auto issue = [&](int qtile, int buf) {
        int n0 = qtile * 128;
        #pragma unroll
        for (int i = tid; i < 2048; i += 256) {
            int r = i >> 4, c = (i & 15) << 2;
            cpa16(qs_b + ((buf * 128 + r) * 72 + c) * 4, Qp + (size_t)(n0 + r) * HD_SZ + c);
        }
        if (tid < 32) cpa16(rs_b + (buf * 128 + tid * 4) * 4, Rp + n0 + tid * 4);
        cp_commit();
    };

    issue(0, 0);
    cp_wait<0>();
    __syncthreads();

    float rs[2][2] = {};

    for (int i = 0; i < 16; i++) {
        int buf = i & 1;
        if (i + 1 < 16) { issue(i + 1, 1 - buf); cp_wait<1>(); }
        else cp_wait<0>();
        __syncthreads();

        float acc[2][8][4] = {};
        #pragma unroll
        for (int k8 = 0; k8 < 8; k8++) {
            int kk = k8 * 8;
            unsigned a[2][4], b[8][2];
            #pragma unroll
            for (int mi = 0; mi < 2; mi++) {
                int rr = wm * 32 + mi * 16;
                float2 fa0 = ((const float2*)&Kr[rr + g][kk])[t];
                float2 fa1 = ((const float2*)&Kr[rr + g + 8][kk])[t];
                a[mi][0] = __float_as_uint(fa0.x); a[mi][2] = __float_as_uint(fa0.y);
                a[mi][1] = __float_as_uint(fa1.x); a[mi][3] = __float_as_uint(fa1.y);
            }
            #pragma unroll
            for (int nj = 0; nj < 8; nj++) {
                int cc = wn * 64 + nj * 8;
                float2 fb = ((const float2*)&Qs[buf][cc + g][kk])[t];
                b[nj][0] = __float_as_uint(fb.x); b[nj][1] = __float_as_uint(fb.y);
            }
            #pragma unroll
            for (int mi = 0; mi < 2; mi++)
                #pragma unroll
                for (int nj = 0; nj < 8; nj++)
                    mma8(acc[mi][nj], a[mi], b[nj]);
        }

        #pragma unroll
        for (int nj = 0; nj < 8; nj++) {
            int cb = wn * 64 + nj * 8 + 2 * t;
            float r0 = rsm[buf][cb], r1 = rsm[buf][cb + 1];
            #pragma unroll
            for (int mi = 0; mi < 2; mi++) {
                rs[mi][0] = fmaf(ex2(acc[mi][nj][0]), r0, rs[mi][0]);
                rs[mi][0] = fmaf(ex2(acc[mi][nj][1]), r1, rs[mi][0]);
                rs[mi][1] = fmaf(ex2(acc[mi][nj][2]), r0, rs[mi][1]);
                rs[mi][1] = fmaf(ex2(acc[mi][nj][3]), r1, rs[mi][1]);
            }
        }
        __syncthreads();
    }

    #pragma unroll
    for (int mi = 0; mi < 2; mi++)
        #pragma unroll
        for (int h2 = 0; h2 < 2; h2++) {
            float v = rs[mi][h2];
            v += __shfl_xor_sync(0xffffffffu, v, 1);
            v += __shfl_xor_sync(0xffffffffu, v, 2);
            if (t == 0) red[wn][wm * 32 + mi * 16 + g + 8 * h2] = v;
        }
    __syncthreads();
    if (tid < 128)
        g_w[bh * S_SZ + k0 + tid] = (red[0][tid] + red[1][tid]) * (1.0f / S_SZ);
}

// ---------------------------------------------------------------------------
// Output: out[b, h*64+d] = sum_k w[bh,k] * V[bh,k,d]. One block per bh.
// ---------------------------------------------------------------------------
__global__ __launch_bounds__(256) void outk(float* __restrict__ out) {
    __shared__ float red2[4][64];
    const int bh = blockIdx.x, tid = threadIdx.x;
    const int d = tid & 63, sl = tid >> 6;
    const float* Vp = g_V + (size_t)bh * S_SZ * HD_SZ;
    const float* wp = g_w + bh * S_SZ;
    float a = 0.f;
    #pragma unroll 4
    for (int k = sl * 512; k < (sl + 1) * 512; ++k)
        a = fmaf(wp[k], Vp[(size_t)k * HD_SZ + d], a);
    red2[sl][d] = a;
    __syncthreads();
    if (tid < 64) {
        float s = red2[0][tid] + red2[1][tid] + red2[2][tid] + red2[3][tid];
        int bb = bh >> 4, h = bh & 15;
        out[bb * D_SZ + h * HD_SZ + tid] = s;
    }
}

// ---------------------------------------------------------------------------
extern "C" void kernel_launch(void* const* d_in, const int* in_sizes, int n_in,
                              void* d_out, int out_size) {
    (void)in_sizes; (void)n_in; (void)out_size;
    const float* X  = (const float*)d_in[0];
    const float* Wq = (const float*)d_in[1];
    const float* bq = (const float*)d_in[2];
    const float* Wk = (const float*)d_in[3];
    const float* bk = (const float*)d_in[4];
    const float* Wv = (const float*)d_in[5];
    const float* bv = (const float*)d_in[6];
    float* out = (float*)d_out;

    cudaFuncSetAttribute(proj_mma, cudaFuncAttributeMaxDynamicSharedMemorySize, PROJ_SMEM);
    cudaFuncSetAttribute(lse_mma,  cudaFuncAttributeMaxDynamicSharedMemorySize, LSE_SMEM);
    cudaFuncSetAttribute(wk_mma,   cudaFuncAttributeMaxDynamicSharedMemorySize, WK_SMEM);

    prep_kernel<<<1024, 256>>>(X, Wq, Wk, Wv);

    dim3 gproj(D_SZ / 128, TOK_SZ / 128, 3);   // (8, 32, 3)
    proj_mma<<<gproj, 256, PROJ_SMEM>>>(bq, bk, bv);

    dim3 ga(S_SZ / 128, BH_SZ);                // (16, 32)
    lse_mma<<<ga, 256, LSE_SMEM>>>();
    wk_mma<<<ga, 256, WK_SMEM>>>();

    outk<<<BH_SZ, 256>>>(out);
}

// round 8
// speedup vs baseline: 6.3400x; 1.3136x over previous
#include <cuda_runtime.h>
#include <cuda_fp16.h>
#include <cstdint>

#define S_SZ 2048
#define D_SZ 1024
#define H_SZ 16
#define HD_SZ 64
#define B_SZ 2
#define BH_SZ (B_SZ * H_SZ)       // 32
#define TOK_SZ (B_SZ * S_SZ)      // 4096
#define KLOG 0.18033688011112042f // 0.125 * log2(e)
#define KSTR 80                   // halves per row in attention smem tiles

// Scratch (device globals: allocation-free rule)
__device__ float  g_Xt[TOK_SZ * D_SZ];        // tf32-rounded X
__device__ float  g_Wt[3 * D_SZ * D_SZ];      // tf32-rounded Wq,Wk,Wv
__device__ __half g_Qh[BH_SZ * S_SZ * HD_SZ]; // fp16, KLOG-scaled, k16-permuted d
__device__ __half g_Kh[BH_SZ * S_SZ * HD_SZ]; // fp16, k16-permuted d
__device__ float  g_V[BH_SZ * S_SZ * HD_SZ];  // full fp32
__device__ float  g_Ri[BH_SZ * S_SZ];         // 1 / rowsum(exp2(scores2))
__device__ float  g_w[BH_SZ * S_SZ];          // mean attention weight per key

// ---------------------------------------------------------------------------
__device__ __forceinline__ float to_tf32(float x) {
    unsigned u; asm("cvt.rna.tf32.f32 %0, %1;" : "=r"(u) : "f"(x));
    return __uint_as_float(u);
}

__device__ __forceinline__ void mma8(float c[4], const unsigned a[4], const unsigned b[2]) {
    asm volatile(
        "mma.sync.aligned.m16n8k8.row.col.f32.tf32.tf32.f32 "
        "{%0,%1,%2,%3}, {%4,%5,%6,%7}, {%8,%9}, {%0,%1,%2,%3};\n"
        : "+f"(c[0]), "+f"(c[1]), "+f"(c[2]), "+f"(c[3])
        : "r"(a[0]), "r"(a[1]), "r"(a[2]), "r"(a[3]), "r"(b[0]), "r"(b[1]));
}

__device__ __forceinline__ void mma16h(float c[4], const unsigned a[4], const unsigned b[2]) {
    asm volatile(
        "mma.sync.aligned.m16n8k16.row.col.f32.f16.f16.f32 "
        "{%0,%1,%2,%3}, {%4,%5,%6,%7}, {%8,%9}, {%0,%1,%2,%3};\n"
        : "+f"(c[0]), "+f"(c[1]), "+f"(c[2]), "+f"(c[3])
        : "r"(a[0]), "r"(a[1]), "r"(a[2]), "r"(a[3]), "r"(b[0]), "r"(b[1]));
}

// 2^x on the MUFU pipe (input already in log2 domain).
__device__ __forceinline__ float ex2(float x) {
    float y; asm("ex2.approx.f32 %0, %1;" : "=f"(y) : "f"(x)); return y;
}

__device__ __forceinline__ void cpa16(uint32_t dst, const void* src) {
    asm volatile("cp.async.ca.shared.global [%0], [%1], 16;\n" :: "r"(dst), "l"(src));
}
__device__ __forceinline__ void cp_commit() { asm volatile("cp.async.commit_group;\n"); }
template <int N> __device__ __forceinline__ void cp_wait() {
    asm volatile("cp.async.wait_group %0;\n" :: "n"(N));
}

// ---------------------------------------------------------------------------
// Prep: round X and the three W matrices to tf32 bits (for the projections).
// ---------------------------------------------------------------------------
__global__ __launch_bounds__(256) void prep_kernel(const float* __restrict__ X,
                                                   const float* __restrict__ Wq,
                                                   const float* __restrict__ Wk,
                                                   const float* __restrict__ Wv) {
    const int NX = TOK_SZ * D_SZ / 4, NW = D_SZ * D_SZ / 4;
    int stride = gridDim.x * blockDim.x;
    for (int i = blockIdx.x * blockDim.x + threadIdx.x; i < NX; i += stride) {
        float4 v = ((const float4*)X)[i];
        v.x = to_tf32(v.x); v.y = to_tf32(v.y); v.z = to_tf32(v.z); v.w = to_tf32(v.w);
        ((float4*)g_Xt)[i] = v;
    }
    for (int w = 0; w < 3; w++) {
        const float* Wp = (w == 0) ? Wq : (w == 1) ? Wk : Wv;
        float4* outp = (float4*)(g_Wt + (size_t)w * D_SZ * D_SZ);
        for (int i = blockIdx.x * blockDim.x + threadIdx.x; i < NW; i += stride) {
            float4 v = ((const float4*)Wp)[i];
            v.x = to_tf32(v.x); v.y = to_tf32(v.y); v.z = to_tf32(v.z); v.w = to_tf32(v.w);
            outp[i] = v;
        }
    }
}

// ---------------------------------------------------------------------------
// Projection (tf32): 128x128 tile, K-chunks of 32, cp.async double-buffered.
// Q/K epilogue converts to fp16 with the k16 permutation
// slot(r) = 4*((r&7)>>1) + ((r>>3)<<1) + (r&1) within each 16-wide d-group,
// so attention fragments are single LDS.64 loads.
// ---------------------------------------------------------------------------
#define PROJ_SMEM ((2 * 128 * 36 + 2 * 32 * 136) * 4)
__global__ __launch_bounds__(256, 2) void proj_mma(const float* __restrict__ bq,
                                                   const float* __restrict__ bk,
                                                   const float* __restrict__ bv) {
    extern __shared__ float sm[];
    float (*Xs)[128][36] = (float(*)[128][36])sm;
    float (*Ws)[32][136] = (float(*)[32][136])(sm + 2 * 128 * 36);

    const int tid = threadIdx.x, lane = tid & 31, wid = tid >> 5;
    const int wm = wid >> 1, wn = wid & 1;
    const int g = lane >> 2, t = lane & 3;
    const int n0 = blockIdx.x * 128, m0 = blockIdx.y * 128, sel = blockIdx.z;
    const float* Xp = g_Xt;
    const float* Wp = g_Wt + (size_t)sel * D_SZ * D_SZ;
    const float* bias = (sel == 0) ? bq : (sel == 1) ? bk : bv;

    uint32_t xs_b = (uint32_t)__cvta_generic_to_shared(&Xs[0][0][0]);
    uint32_t ws_b = (uint32_t)__cvta_generic_to_shared(&Ws[0][0][0]);

    auto issue = [&](int ktile, int buf) {
        int k0 = ktile * 32;
        #pragma unroll
        for (int i = tid; i < 1024; i += 256) {   // X tile 128x32
            int r = i >> 3, c = (i & 7) << 2;
            cpa16(xs_b + ((buf * 128 + r) * 36 + c) * 4, Xp + (size_t)(m0 + r) * D_SZ + k0 + c);
        }
        #pragma unroll
        for (int i = tid; i < 1024; i += 256) {   // W tile 32x128
            int r = i >> 5, c = (i & 31) << 2;
            cpa16(ws_b + ((buf * 32 + r) * 136 + c) * 4, Wp + (size_t)(k0 + r) * D_SZ + n0 + c);
        }
        cp_commit();
    };

    float acc[2][8][4] = {};
    issue(0, 0);

    for (int i = 0; i < 32; i++) {
        int buf = i & 1;
        if (i + 1 < 32) { issue(i + 1, 1 - buf); cp_wait<1>(); }
        else cp_wait<0>();
        __syncthreads();

        #pragma unroll
        for (int kk = 0; kk < 32; kk += 8) {
            unsigned a[2][4], b[8][2];
            #pragma unroll
            for (int mi = 0; mi < 2; mi++) {
                int rr = wm * 32 + mi * 16;
                a[mi][0] = __float_as_uint(Xs[buf][rr + g][kk + t]);
                a[mi][1] = __float_as_uint(Xs[buf][rr + g + 8][kk + t]);
                a[mi][2] = __float_as_uint(Xs[buf][rr + g][kk + t + 4]);
                a[mi][3] = __float_as_uint(Xs[buf][rr + g + 8][kk + t + 4]);
            }
            #pragma unroll
            for (int nj = 0; nj < 8; nj++) {
                int cc = wn * 64 + nj * 8;
                b[nj][0] = __float_as_uint(Ws[buf][kk + t][cc + g]);
                b[nj][1] = __float_as_uint(Ws[buf][kk + t + 4][cc + g]);
            }
            #pragma unroll
            for (int mi = 0; mi < 2; mi++)
                #pragma unroll
                for (int nj = 0; nj < 8; nj++)
                    mma8(acc[mi][nj], a[mi], b[nj]);
        }
        __syncthreads();
    }

    #pragma unroll
    for (int mi = 0; mi < 2; mi++) {
        int row = m0 + wm * 32 + mi * 16 + g;
        int bb = row >> 11, s = row & (S_SZ - 1);
        #pragma unroll
        for (int nj = 0; nj < 8; nj++) {
            int col = n0 + wn * 64 + nj * 8 + 2 * t;
            int h = col >> 6, d = col & 63;
            float b0 = bias[col], b1 = bias[col + 1];
            float v0 = acc[mi][nj][0] + b0, v1 = acc[mi][nj][1] + b1;
            float v2 = acc[mi][nj][2] + b0, v3 = acc[mi][nj][3] + b1;
            size_t base0 = ((size_t)(bb * H_SZ + h) * S_SZ + s) * HD_SZ;
            size_t base1 = ((size_t)(bb * H_SZ + h) * S_SZ + s + 8) * HD_SZ;
            if (sel == 2) {
                *(float2*)(g_V + base0 + d) = make_float2(v0, v1);
                *(float2*)(g_V + base1 + d) = make_float2(v2, v3);
            } else {
                if (sel == 0) { v0 *= KLOG; v1 *= KLOG; v2 *= KLOG; v3 *= KLOG; }
                __half* hp = (sel == 0) ? g_Qh : g_Kh;
                int grp = d >> 4, r16 = d & 15;
                int slot = 4 * ((r16 & 7) >> 1) + ((r16 >> 3) << 1);   // d even
                size_t o = grp * 16 + slot;
                *(__half2*)(hp + base0 + o) = __floats2half2_rn(v0, v1);
                *(__half2*)(hp + base1 + o) = __floats2half2_rn(v2, v3);
            }
        }
    }
}

// ---------------------------------------------------------------------------
// Pass A (lse): resident A = Q' (128 q-rows, fp16), streamed B = K (fp16).
// m16n8k16; every fragment is one LDS.64 (stride 80 halves, conflict-free).
// ---------------------------------------------------------------------------
#define LSE_SMEM (128 * KSTR * 2 + 2 * 128 * KSTR * 2 + 2 * 128 * 4)
__global__ __launch_bounds__(256, 2) void lse_mma() {
    extern __shared__ char smc[];
    __half (*Qs)[KSTR] = (__half(*)[KSTR])smc;
    __half (*Ks)[128][KSTR] = (__half(*)[128][KSTR])(smc + 128 * KSTR * 2);
    float (*red)[128] = (float(*)[128])(smc + 128 * KSTR * 2 + 2 * 128 * KSTR * 2);

    const int tid = threadIdx.x, lane = tid & 31, wid = tid >> 5;
    const int wm = wid >> 1, wn = wid & 1;
    const int g = lane >> 2, t = lane & 3;
    const int bh = blockIdx.y, q0 = blockIdx.x * 128;
    const __half* Qp = g_Qh + (size_t)bh * S_SZ * HD_SZ;
    const __half* Kp = g_Kh + (size_t)bh * S_SZ * HD_SZ;

    uint32_t qs_b = (uint32_t)__cvta_generic_to_shared(&Qs[0][0]);
    uint32_t ks_b = (uint32_t)__cvta_generic_to_shared(&Ks[0][0][0]);

    #pragma unroll
    for (int i = tid; i < 1024; i += 256) {        // 128 rows x 64 halves
        int r = i >> 3, c8 = (i & 7) << 3;
        cpa16(qs_b + (r * KSTR + c8) * 2, Qp + (size_t)(q0 + r) * HD_SZ + c8);
    }
    cp_commit();

    auto issue = [&](int ktile, int buf) {
        int n0 = ktile * 128;
        #pragma unroll
        for (int i = tid; i < 1024; i += 256) {
            int r = i >> 3, c8 = (i & 7) << 3;
            cpa16(ks_b + ((buf * 128 + r) * KSTR + c8) * 2, Kp + (size_t)(n0 + r) * HD_SZ + c8);
        }
        cp_commit();
    };

    issue(0, 0);
    cp_wait<0>();
    __syncthreads();

    float rs[2][2] = {};

    for (int i = 0; i < 16; i++) {
        int buf = i & 1;
        if (i + 1 < 16) { issue(i + 1, 1 - buf); cp_wait<1>(); }
        else cp_wait<0>();
        __syncthreads();

        float acc[2][8][4] = {};
        #pragma unroll
        for (int k16 = 0; k16 < 4; k16++) {
            int kk = k16 * 16 + 4 * t;
            unsigned a[2][4], b[8][2];
            #pragma unroll
            for (int mi = 0; mi < 2; mi++) {
                int rr = wm * 32 + mi * 16;
                uint2 w0 = *(const uint2*)&Qs[rr + g][kk];
                uint2 w1 = *(const uint2*)&Qs[rr + g + 8][kk];
                a[mi][0] = w0.x; a[mi][1] = w1.x; a[mi][2] = w0.y; a[mi][3] = w1.y;
            }
            #pragma unroll
            for (int nj = 0; nj < 8; nj++) {
                int cc = wn * 64 + nj * 8;
                uint2 wb = *(const uint2*)&Ks[buf][cc + g][kk];
                b[nj][0] = wb.x; b[nj][1] = wb.y;
            }
            #pragma unroll
            for (int mi = 0; mi < 2; mi++)
                #pragma unroll
                for (int nj = 0; nj < 8; nj++)
                    mma16h(acc[mi][nj], a[mi], b[nj]);
        }

        #pragma unroll
        for (int mi = 0; mi < 2; mi++)
            #pragma unroll
            for (int nj = 0; nj < 8; nj++) {
                rs[mi][0] += ex2(acc[mi][nj][0]) + ex2(acc[mi][nj][1]);
                rs[mi][1] += ex2(acc[mi][nj][2]) + ex2(acc[mi][nj][3]);
            }
        __syncthreads();
    }

    #pragma unroll
    for (int mi = 0; mi < 2; mi++)
        #pragma unroll
        for (int h2 = 0; h2 < 2; h2++) {
            float v = rs[mi][h2];
            v += __shfl_xor_sync(0xffffffffu, v, 1);
            v += __shfl_xor_sync(0xffffffffu, v, 2);
            if (t == 0) red[wn][wm * 32 + mi * 16 + g + 8 * h2] = v;
        }
    __syncthreads();
    if (tid < 128)
        g_Ri[bh * S_SZ + q0 + tid] = 1.0f / (red[0][tid] + red[1][tid]);
}

// ---------------------------------------------------------------------------
// Pass B (wk): resident A = K (128 keys, fp16), streamed B = Q' + Ri.
// w[k] = (1/S) * sum_q exp2(score2) * Ri[q].
// ---------------------------------------------------------------------------
#define WK_SMEM (128 * KSTR * 2 + 2 * 128 * KSTR * 2 + 2 * 128 * 4 + 2 * 128 * 4)
__global__ __launch_bounds__(256, 2) void wk_mma() {
    extern __shared__ char smc[];
    __half (*Kr)[KSTR] = (__half(*)[KSTR])smc;
    __half (*Qs)[128][KSTR] = (__half(*)[128][KSTR])(smc + 128 * KSTR * 2);
    float (*rsm)[128] = (float(*)[128])(smc + 128 * KSTR * 2 + 2 * 128 * KSTR * 2);
    float (*red)[128] = (float(*)[128])(smc + 128 * KSTR * 2 + 2 * 128 * KSTR * 2 + 2 * 128 * 4);

    const int tid = threadIdx.x, lane = tid & 31, wid = tid >> 5;
    const int wm = wid >> 1, wn = wid & 1;
    const int g = lane >> 2, t = lane & 3;
    const int bh = blockIdx.y, k0 = blockIdx.x * 128;
    const __half* Qp = g_Qh + (size_t)bh * S_SZ * HD_SZ;
    const __half* Kp = g_Kh + (size_t)bh * S_SZ * HD_SZ;
    const float* Rp = g_Ri + bh * S_SZ;

    uint32_t kr_b = (uint32_t)__cvta_generic_to_shared(&Kr[0][0]);
    uint32_t qs_b = (uint32_t)__cvta_generic_to_shared(&Qs[0][0][0]);
    uint32_t rs_b = (uint32_t)__cvta_generic_to_shared(&rsm[0][0]);

    #pragma unroll
    for (int i = tid; i < 1024; i += 256) {
        int r = i >> 3, c8 = (i & 7) << 3;
        cpa16(kr_b + (r * KSTR + c8) * 2, Kp + (size_t)(k0 + r) * HD_SZ + c8);
    }
    cp_commit();

    auto issue = [&](int qtile, int buf) {
        int n0 = qtile * 128;
        #pragma unroll
        for (int i = tid; i < 1024; i += 256) {
            int r = i >> 3, c8 = (i & 7) << 3;
            cpa16(qs_b + ((buf * 128 + r) * KSTR + c8) * 2, Qp + (size_t)(n0 + r) * HD_SZ + c8);
        }
        if (tid < 32) cpa16(rs_b + (buf * 128 + tid * 4) * 4, Rp + n0 + tid * 4);
        cp_commit();
    };

    issue(0, 0);
    cp_wait<0>();
    __syncthreads();

    float rs[2][2] = {};

    for (int i = 0; i < 16; i++) {
        int buf = i & 1;
        if (i + 1 < 16) { issue(i + 1, 1 - buf); cp_wait<1>(); }
        else cp_wait<0>();
        __syncthreads();

        float acc[2][8][4] = {};
        #pragma unroll
        for (int k16 = 0; k16 < 4; k16++) {
            int kk = k16 * 16 + 4 * t;
            unsigned a[2][4], b[8][2];
            #pragma unroll
            for (int mi = 0; mi < 2; mi++) {
                int rr = wm * 32 + mi * 16;
                uint2 w0 = *(const uint2*)&Kr[rr + g][kk];
                uint2 w1 = *(const uint2*)&Kr[rr + g + 8][kk];
                a[mi][0] = w0.x; a[mi][1] = w1.x; a[mi][2] = w0.y; a[mi][3] = w1.y;
            }
            #pragma unroll
            for (int nj = 0; nj < 8; nj++) {
                int cc = wn * 64 + nj * 8;
                uint2 wb = *(const uint2*)&Qs[buf][cc + g][kk];
                b[nj][0] = wb.x; b[nj][1] = wb.y;
            }
            #pragma unroll
            for (int mi = 0; mi < 2; mi++)
                #pragma unroll
                for (int nj = 0; nj < 8; nj++)
                    mma16h(acc[mi][nj], a[mi], b[nj]);
        }

        #pragma unroll
        for (int nj = 0; nj < 8; nj++) {
            int cb = wn * 64 + nj * 8 + 2 * t;
            float r0 = rsm[buf][cb], r1 = rsm[buf][cb + 1];
            #pragma unroll
            for (int mi = 0; mi < 2; mi++) {
                rs[mi][0] = fmaf(ex2(acc[mi][nj][0]), r0, rs[mi][0]);
                rs[mi][0] = fmaf(ex2(acc[mi][nj][1]), r1, rs[mi][0]);
                rs[mi][1] = fmaf(ex2(acc[mi][nj][2]), r0, rs[mi][1]);
                rs[mi][1] = fmaf(ex2(acc[mi][nj][3]), r1, rs[mi][1]);
            }
        }
        __syncthreads();
    }

    #pragma unroll
    for (int mi = 0; mi < 2; mi++)
        #pragma unroll
        for (int h2 = 0; h2 < 2; h2++) {
            float v = rs[mi][h2];
            v += __shfl_xor_sync(0xffffffffu, v, 1);
            v += __shfl_xor_sync(0xffffffffu, v, 2);
            if (t == 0) red[wn][wm * 32 + mi * 16 + g + 8 * h2] = v;
        }
    __syncthreads();
    if (tid < 128)
        g_w[bh * S_SZ + k0 + tid] = (red[0][tid] + red[1][tid]) * (1.0f / S_SZ);
}

// ---------------------------------------------------------------------------
// Output: out[b, h*64+d] = sum_k w[bh,k] * V[bh,k,d]. One block per bh.
// ---------------------------------------------------------------------------
__global__ __launch_bounds__(256) void outk(float* __restrict__ out) {
    __shared__ float red2[4][64];
    const int bh = blockIdx.x, tid = threadIdx.x;
    const int d = tid & 63, sl = tid >> 6;
    const float* Vp = g_V + (size_t)bh * S_SZ * HD_SZ;
    const float* wp = g_w + bh * S_SZ;
    float a = 0.f;
    #pragma unroll 4
    for (int k = sl * 512; k < (sl + 1) * 512; ++k)
        a = fmaf(wp[k], Vp[(size_t)k * HD_SZ + d], a);
    red2[sl][d] = a;
    __syncthreads();
    if (tid < 64) {
        float s = red2[0][tid] + red2[1][tid] + red2[2][tid] + red2[3][tid];
        int bb = bh >> 4, h = bh & 15;
        out[bb * D_SZ + h * HD_SZ + tid] = s;
    }
}

// ---------------------------------------------------------------------------
extern "C" void kernel_launch(void* const* d_in, const int* in_sizes, int n_in,
                              void* d_out, int out_size) {
    (void)in_sizes; (void)n_in; (void)out_size;
    const float* X  = (const float*)d_in[0];
    const float* Wq = (const float*)d_in[1];
    const float* bq = (const float*)d_in[2];
    const float* Wk = (const float*)d_in[3];
    const float* bk = (const float*)d_in[4];
    const float* Wv = (const float*)d_in[5];
    const float* bv = (const float*)d_in[6];
    float* out = (float*)d_out;

    cudaFuncSetAttribute(proj_mma, cudaFuncAttributeMaxDynamicSharedMemorySize, PROJ_SMEM);
    cudaFuncSetAttribute(lse_mma,  cudaFuncAttributeMaxDynamicSharedMemorySize, LSE_SMEM);
    cudaFuncSetAttribute(wk_mma,   cudaFuncAttributeMaxDynamicSharedMemorySize, WK_SMEM);

    prep_kernel<<<1024, 256>>>(X, Wq, Wk, Wv);

    dim3 gproj(D_SZ / 128, TOK_SZ / 128, 3);   // (8, 32, 3)
    proj_mma<<<gproj, 256, PROJ_SMEM>>>(bq, bk, bv);

    dim3 ga(S_SZ / 128, BH_SZ);                // (16, 32)
    lse_mma<<<ga, 256, LSE_SMEM>>>();
    wk_mma<<<ga, 256, WK_SMEM>>>();

    outk<<<BH_SZ, 256>>>(out);
}